// round 7
// baseline (speedup 1.0000x reference)
#include <cuda_runtime.h>
#include <math.h>

#define Mmod 16
#define Tlen 512
#define Dd   512
#define Hh   512
#define QKd  256
#define Gg   2048   /* 4*H */
#define KACT 4
#define NB   148    /* persistent blocks; <= SM count, 1 block/SM guaranteed */

// ---------------- scratch (device globals; no allocation allowed) ------------
__device__ float g_keyx[Tlen*Mmod*QKd];   // [t][m][k]          8 MB
__device__ float g_val1[Mmod*Tlen*Dd];    // [m][t][d]         16 MB
__device__ float g_P[Tlen*Mmod*Gg];       // [t][m][g]         64 MB
__device__ float g_Pb[Mmod*Gg];
__device__ float g_Cb[Mmod*Gg];
__device__ float g_h[Mmod*Hh];
__device__ float g_c[Mmod*Hh];
__device__ float g_temph[Mmod*Hh];
__device__ float g_zhh[Mmod*Gg];
__device__ float g_qbuf[Mmod*QKd];
__device__ float g_q2[Mmod*Hh];
__device__ float g_k2[Mmod*Hh];
__device__ float g_v2[Mmod*Hh];
__device__ int   g_barCnt;
__device__ int   g_barGen;

// ---------------- init: zero state + output + barrier ------------------------
__global__ void k_init(float* __restrict__ out, long long out_size)
{
    long long i = (long long)blockIdx.x*blockDim.x + threadIdx.x;
    long long stride = (long long)gridDim.x*blockDim.x;
    for (long long j=i; j<out_size; j+=stride) out[j]=0.f;
    for (long long j=i; j<Mmod*Hh; j+=stride){ g_h[j]=0.f; g_c[j]=0.f; }
    if (i==0){ g_barCnt=0; g_barGen=0; }
}

// ---------------- fp32 SGEMM: C[i,j] = sum_k A[i,k]*B[j,k] (+bias[j]) --------
__global__ __launch_bounds__(256) void sgemm128(
    const float* __restrict__ Aext, int useValA, long long strideAm,
    const float* __restrict__ Bbase, long long strideBm,
    const float* __restrict__ biasBase, int strideBias, int hasBias,
    int dstSel, long long strideCm, int ldc, int K)
{
    const int m  = blockIdx.z;
    const float* A = (useValA ? (const float*)g_val1 : Aext) + (long long)m*strideAm;
    const float* B = Bbase + (long long)m*strideBm;
    float* C = (dstSel==0 ? g_keyx : (dstSel==1 ? g_val1 : g_P)) + (long long)m*strideCm;

    const int i0 = blockIdx.y*128, j0 = blockIdx.x*128;
    __shared__ __align__(16) float As[8][128];
    __shared__ __align__(16) float Bs[8][128];
    const int tid = threadIdx.x;
    const int arow = tid>>1, acol = (tid&1)*4;
    const int tx = tid & 15, ty = tid >> 4;

    float acc[8][8];
    #pragma unroll
    for (int r=0;r<8;r++)
        #pragma unroll
        for (int c=0;c<8;c++) acc[r][c]=0.f;

    for (int kk=0; kk<K; kk+=8){
        float4 av = *(const float4*)(A + (long long)(i0+arow)*K + kk + acol);
        float4 bv = *(const float4*)(B + (long long)(j0+arow)*K + kk + acol);
        __syncthreads();
        As[acol+0][arow]=av.x; As[acol+1][arow]=av.y; As[acol+2][arow]=av.z; As[acol+3][arow]=av.w;
        Bs[acol+0][arow]=bv.x; Bs[acol+1][arow]=bv.y; Bs[acol+2][arow]=bv.z; Bs[acol+3][arow]=bv.w;
        __syncthreads();
        #pragma unroll
        for (int k=0;k<8;k++){
            float ar[8], br[8];
            *(float4*)&ar[0] = *(const float4*)&As[k][ty*8];
            *(float4*)&ar[4] = *(const float4*)&As[k][ty*8+4];
            *(float4*)&br[0] = *(const float4*)&Bs[k][tx*8];
            *(float4*)&br[4] = *(const float4*)&Bs[k][tx*8+4];
            #pragma unroll
            for (int r=0;r<8;r++)
                #pragma unroll
                for (int c=0;c<8;c++) acc[r][c] += ar[r]*br[c];
        }
    }
    #pragma unroll
    for (int r=0;r<8;r++){
        const int i = i0 + ty*8 + r;
        #pragma unroll
        for (int c=0;c<8;c++){
            const int j = j0 + tx*8 + c;
            float v = acc[r][c];
            if (hasBias) v += biasBase[(long long)m*strideBias + j];
            C[(long long)i*ldc + j] = v;
        }
    }
}

// ---------------- Pb[m,g] = bv[m]·W_ih[m,g,:];  Cb = b_ih + b_hh + Pb --------
__global__ __launch_bounds__(256) void k_pbcb(
    const float* __restrict__ bv, const float* __restrict__ Wih,
    const float* __restrict__ bih, const float* __restrict__ bhh)
{
    const int w = (blockIdx.x*blockDim.x + threadIdx.x) >> 5;
    const int lane = threadIdx.x & 31;
    if (w >= Mmod*Gg) return;
    const int m = w >> 11;
    const float* wrow = Wih + (long long)w*Dd;
    const float* bvr  = bv + (long long)m*Dd;
    float acc=0.f;
    #pragma unroll
    for (int i=0;i<4;i++){
        float4 a = *(const float4*)(wrow + (lane+32*i)*4);
        float4 b = *(const float4*)(bvr  + (lane+32*i)*4);
        acc += a.x*b.x + a.y*b.y + a.z*b.z + a.w*b.w;
    }
    #pragma unroll
    for (int off=16;off;off>>=1) acc += __shfl_down_sync(0xffffffffu, acc, off);
    if (lane==0){
        g_Pb[w] = acc;
        g_Cb[w] = acc + bih[w] + bhh[w];
    }
}

// ---------------- grid barrier (all NB blocks resident in one wave) ----------
__device__ __forceinline__ void gridbar(int& gen)
{
    __threadfence();
    __syncthreads();
    if (threadIdx.x == 0){
        if (atomicAdd(&g_barCnt, 1) == NB-1){
            atomicExch(&g_barCnt, 0);
            __threadfence();
            atomicAdd(&g_barGen, 1);
        } else {
            while (atomicAdd(&g_barGen, 0) == gen) __nanosleep(32);
        }
    }
    __syncthreads();
    gen++;
}

// ---------------- persistent step loop ---------------------------------------
__global__ __launch_bounds__(256,1) void k_loop(
    const float* __restrict__ Wq,  const float* __restrict__ bq,
    const float* __restrict__ bk,  const float* __restrict__ Whh,
    const float* __restrict__ Wqg, const float* __restrict__ Wkg,
    const float* __restrict__ Wvg,
    float* __restrict__ out, long long osz)
{
    __shared__ __align__(16) float sh[Mmod*Hh];   // staging: h, then temp_h (32KB)
    __shared__ __align__(16) float q2s[Hh];
    __shared__ float att0s[Mmod], att1s[Mmod], sl[Mmod], att2s[Mmod];
    __shared__ int   act[Mmod];
    __shared__ float red[64];

    const int tid  = threadIdx.x;
    const int lane = tid & 31, wid = tid >> 5;
    const int gid  = blockIdx.x*256 + tid;
    const int gw   = blockIdx.x*8 + wid;          // global warp id, 0..NB*8-1
    int gen = 0;

    const int ROWS1 = Mmod*Gg + Mmod*QKd;          // 32768 z rows + 4096 q rows
    const int PER1  = (ROWS1 + NB*8 - 1)/(NB*8);   // 32

    for (int t=0; t<Tlen; t++){
        // ---- stage h (written by F across blocks; L2-scope read) ----
        for (int i=tid; i<Mmod*Hh; i+=256) sh[i] = __ldcg(&g_h[i]);
        __syncthreads();

        // ---- phase 1: z_hh = h@W_hh ; q = h@Wq + bq  (warp per row, 4-way) ----
        {
            int r    = gw*PER1;
            int rend = r + PER1; if (rend > ROWS1) rend = ROWS1;
            while (r < rend){
                int nr = rend - r; if (nr > 4) nr = 4;
                const float* wr[4]; int mrow[4]; float* dst[4]; float bias[4];
                #pragma unroll
                for (int j=0;j<4;j++){
                    int rr = r + (j < nr ? j : 0);
                    if (rr < Mmod*Gg){
                        wr[j] = Whh + (long long)rr*Hh;
                        mrow[j] = rr >> 11;
                        dst[j] = &g_zhh[rr];
                        bias[j] = 0.f;
                    } else {
                        int idx = rr - Mmod*Gg;
                        int m = idx >> 8, k = idx & 255;
                        wr[j] = Wq + ((long long)m*QKd + k)*Hh;
                        mrow[j] = m;
                        dst[j] = &g_qbuf[idx];
                        bias[j] = bq[m*QKd + k];
                    }
                }
                float4 a[4][4];
                #pragma unroll
                for (int j=0;j<4;j++)
                    #pragma unroll
                    for (int i=0;i<4;i++)
                        a[j][i] = *(const float4*)(wr[j] + (lane+32*i)*4);
                float acc[4] = {0.f,0.f,0.f,0.f};
                #pragma unroll
                for (int j=0;j<4;j++)
                    #pragma unroll
                    for (int i=0;i<4;i++){
                        float4 b = *(const float4*)(&sh[mrow[j]*Hh + (lane+32*i)*4]);
                        acc[j] += a[j][i].x*b.x + a[j][i].y*b.y + a[j][i].z*b.z + a[j][i].w*b.w;
                    }
                #pragma unroll
                for (int j=0;j<4;j++){
                    float v = acc[j];
                    #pragma unroll
                    for (int off=16;off;off>>=1) v += __shfl_down_sync(0xffffffffu, v, off);
                    if (lane==0 && j < nr) *dst[j] = v + bias[j];
                }
                r += nr;
            }
        }
        gridbar(gen);

        // ---- att (every block, identical deterministic computation) ----
        for (int m=0;m<Mmod;m++){
            float qv = __ldcg(&g_qbuf[m*QKd + tid]);
            float p0 = qv * bk[m*QKd + tid];
            float p1 = qv * g_keyx[((long long)t*Mmod + m)*QKd + tid];
            #pragma unroll
            for (int off=16;off;off>>=1){
                p0 += __shfl_down_sync(0xffffffffu,p0,off);
                p1 += __shfl_down_sync(0xffffffffu,p1,off);
            }
            if (lane==0){ red[wid]=p0; red[32+wid]=p1; }
            __syncthreads();
            if (tid==0){
                float l0=0.f,l1=0.f;
                for (int w2=0;w2<8;w2++){ l0+=red[w2]; l1+=red[32+w2]; }
                const float scale = 0.0625f;
                l0*=scale; l1*=scale;
                float mx = fmaxf(l0,l1);
                float e0 = expf(l0-mx), e1 = expf(l1-mx);
                float s  = e0+e1;
                att0s[m] = e0/s;
                att1s[m] = e1/s;
            }
            __syncthreads();
        }
        if (tid < Mmod){
            const float my0 = att0s[tid];
            int cnt=0;
            #pragma unroll
            for (int q=0;q<Mmod;q++) cnt += (att0s[q] < my0) || (att0s[q]==my0 && q<tid);
            act[tid] = (cnt < KACT);
        }
        __syncthreads();

        // ---- topk index output (block 0, thread 0) ----
        if (blockIdx.x==0 && tid==0 && osz >= (long long)Tlen*Mmod*Hh + (long long)Tlen*KACT){
            bool used[Mmod];
            #pragma unroll
            for (int q=0;q<Mmod;q++) used[q]=false;
            for (int r2=0;r2<KACT;r2++){
                float best = 3.4e38f; int bi=0;
                for (int q=0;q<Mmod;q++)
                    if (!used[q] && att0s[q] < best){ best=att0s[q]; bi=q; }
                used[bi]=true;
                out[(long long)Tlen*Mmod*Hh + (long long)t*KACT + r2] = (float)bi;
            }
        }

        // ---- phase D: gates / LSTM / temp_h (one element per thread) ----
        if (gid < Mmod*Hh){
            const int m = gid >> 9, j = gid & 511;
            const float att1 = att1s[m];
            const bool active = (act[m] != 0);
            const long long pb = (long long)t*Mmod*Gg + (long long)m*Gg;
            float gv[4];
            #pragma unroll
            for (int q=0;q<4;q++){
                const int g = j + q*Hh;
                gv[q] = g_Cb[m*Gg+g] + att1*(__ldg(&g_P[pb+g]) - g_Pb[m*Gg+g])
                      + __ldcg(&g_zhh[m*Gg+g]);
            }
            const float ig = 1.f/(1.f+expf(-gv[0]));
            const float fg = 1.f/(1.f+expf(-gv[1]));
            const float gg = tanhf(gv[2]);
            const float og = 1.f/(1.f+expf(-gv[3]));
            const float c_old = __ldcg(&g_c[gid]);
            const float cn = fg*c_old + ig*gg;
            const float hn = og*tanhf(cn);
            const float h_old = sh[gid];
            g_temph[gid] = active ? hn : h_old;
            g_c[gid]     = active ? cn : 0.f;
        }
        gridbar(gen);

        // ---- stage temp_h; phase E: q2/k2/v2 = temp_h @ W*_g ----
        for (int i=tid; i<Mmod*Hh; i+=256) sh[i] = __ldcg(&g_temph[i]);
        __syncthreads();
        if (gid < 3*Mmod*Hh){
            const int mat = gid / (Mmod*Hh);
            const int rem = gid - mat*Mmod*Hh;
            const int m = rem >> 9, o = rem & 511;
            const float* W = (mat==0?Wqg:(mat==1?Wkg:Wvg)) + (long long)m*Hh*Hh;
            float* outp = (mat==0?g_q2:(mat==1?g_k2:g_v2));
            float acc[16];
            #pragma unroll
            for (int u=0;u<16;u++) acc[u]=0.f;
            for (int h=0; h<Hh; h+=16){
                #pragma unroll
                for (int u=0;u<16;u++)
                    acc[u] += sh[m*Hh + h+u] * W[(long long)(h+u)*Hh + o];
            }
            float s0 = ((acc[0]+acc[1])+(acc[2]+acc[3])) + ((acc[4]+acc[5])+(acc[6]+acc[7]));
            float s1 = ((acc[8]+acc[9])+(acc[10]+acc[11])) + ((acc[12]+acc[13])+(acc[14]+acc[15]));
            outp[rem] = s0 + s1;
        }
        gridbar(gen);

        // ---- phase F: att2 softmax + combine + new h + output (blocks 0..15) ----
        if (blockIdx.x < Mmod){
            const int a = blockIdx.x;
            for (int i=tid;i<Hh;i+=256) q2s[i] = __ldcg(&g_q2[a*Hh+i]);
            __syncthreads();
            for (int bb=wid*2; bb<wid*2+2; bb++){
                const float* kp = g_k2 + bb*Hh;
                float acc=0.f;
                #pragma unroll
                for (int i=0;i<4;i++){
                    float4 kv4 = __ldcg((const float4*)(kp + (lane+32*i)*4));
                    float4 qv4 = *(const float4*)(&q2s[(lane+32*i)*4]);
                    acc += kv4.x*qv4.x + kv4.y*qv4.y + kv4.z*qv4.z + kv4.w*qv4.w;
                }
                #pragma unroll
                for (int off=16;off;off>>=1) acc += __shfl_down_sync(0xffffffffu, acc, off);
                if (lane==0) sl[bb]=acc;
            }
            __syncthreads();
            if (tid==0){
                float mx=-3.4e38f;
                for (int q=0;q<Mmod;q++) mx = fmaxf(mx, sl[q]);
                float s=0.f;
                for (int q=0;q<Mmod;q++){ float e=expf(sl[q]-mx); att2s[q]=e; s+=e; }
                const float inv = 1.f/s;
                for (int q=0;q<Mmod;q++) att2s[q]*=inv;
            }
            __syncthreads();
            const bool active = (act[a] != 0);
            for (int o=tid;o<Hh;o+=256){
                float v;
                if (active){
                    float s=0.f;
                    #pragma unroll
                    for (int q=0;q<Mmod;q++) s += att2s[q]*__ldcg(&g_v2[q*Hh+o]);
                    v = s + sh[a*Hh+o];          // sh holds temp_h here
                } else {
                    v = __ldcg(&g_h[a*Hh+o]);
                }
                g_h[a*Hh+o]=v;
                out[((long long)t*Mmod + a)*Hh + o] = v;
            }
        }
        gridbar(gen);
    }
}

// ---------------- launch ------------------------------------------------------
extern "C" void kernel_launch(void* const* d_in, const int* in_sizes, int n_in,
                              void* d_out, int out_size)
{
    const float* inputs = (const float*)d_in[0];
    const float* Wq   = (const float*)d_in[1];
    const float* bq   = (const float*)d_in[2];
    const float* Wk   = (const float*)d_in[3];
    const float* bk   = (const float*)d_in[4];
    const float* Wv   = (const float*)d_in[5];
    const float* bv   = (const float*)d_in[6];
    const float* Wih  = (const float*)d_in[7];
    const float* bih  = (const float*)d_in[8];
    const float* Whh  = (const float*)d_in[9];
    const float* bhh  = (const float*)d_in[10];
    const float* Wqg  = (const float*)d_in[11];
    const float* Wkg  = (const float*)d_in[12];
    const float* Wvg  = (const float*)d_in[13];
    float* out = (float*)d_out;
    const long long osz = (long long)out_size;

    k_init<<<1024,256>>>(out, osz);

    // key_x[t,m,k] = x_t @ Wk^T + bk
    {
        dim3 g(QKd/128, Tlen/128, Mmod);
        sgemm128<<<g,256>>>(inputs, 0, (long long)Tlen*Dd,
                            Wk, (long long)QKd*Dd,
                            bk, QKd, 1,
                            0, (long long)QKd, Mmod*QKd, Dd);
    }
    // val1[m,t,v] = x_t @ Wv^T + bv
    {
        dim3 g(Dd/128, Tlen/128, Mmod);
        sgemm128<<<g,256>>>(inputs, 0, (long long)Tlen*Dd,
                            Wv, (long long)Dd*Dd,
                            bv, Dd, 1,
                            1, (long long)Tlen*Dd, Dd, Dd);
    }
    k_pbcb<<<(Mmod*Gg)/8, 256>>>(bv, Wih, bih, bhh);
    // P[t,m,g] = val1 @ W_ih^T
    {
        dim3 g(Gg/128, Tlen/128, Mmod);
        sgemm128<<<g,256>>>(nullptr, 1, (long long)Tlen*Dd,
                            Wih, (long long)Gg*Dd,
                            nullptr, 0, 0,
                            2, (long long)Gg, Mmod*Gg, Dd);
    }

    k_loop<<<NB,256>>>(Wq, bq, bk, Whh, Wqg, Wkg, Wvg, out, osz);
}

// round 8
// speedup vs baseline: 1.7147x; 1.7147x over previous
#include <cuda_runtime.h>
#include <math.h>

#define Mmod 16
#define Tlen 512
#define Dd   512
#define Hh   512
#define QKd  256
#define Gg   2048   /* 4*H */
#define KACT 4
#define NB   148    /* persistent blocks; <= SM count, 1 block/SM guaranteed */

// ---------------- scratch (device globals; no allocation allowed) ------------
__device__ float g_keyx[Tlen*Mmod*QKd];   // [t][m][k]          8 MB
__device__ float g_val1[Mmod*Tlen*Dd];    // [m][t][d]         16 MB
__device__ float g_P[Tlen*Mmod*Gg];       // [t][m][g]         64 MB
__device__ float g_Pb[Mmod*Gg];
__device__ float g_Cb[Mmod*Gg];
__device__ float g_cbuf[2*Mmod*Hh];       // double-buffered c
__device__ float g_temph[Mmod*Hh];
__device__ float g_zhh[Mmod*Gg];
__device__ float g_qbuf[Mmod*QKd];
__device__ float g_q2[Mmod*Hh];
__device__ float g_k2[Mmod*Hh];
__device__ float g_v2[Mmod*Hh];
__device__ int   g_barCnt;
__device__ int   g_barGen;

// ---------------- init ---------------------------------------------------------
__global__ void k_init(float* __restrict__ out, long long out_size)
{
    long long i = (long long)blockIdx.x*blockDim.x + threadIdx.x;
    long long stride = (long long)gridDim.x*blockDim.x;
    for (long long j=i; j<out_size; j+=stride) out[j]=0.f;
    for (long long j=i; j<2*Mmod*Hh; j+=stride) g_cbuf[j]=0.f;
    if (i==0){ g_barCnt=0; g_barGen=0; }
}

// ---------------- fp32 SGEMM: C[i,j] = sum_k A[i,k]*B[j,k] (+bias[j]) --------
__global__ __launch_bounds__(256) void sgemm128(
    const float* __restrict__ Aext, int useValA, long long strideAm,
    const float* __restrict__ Bbase, long long strideBm,
    const float* __restrict__ biasBase, int strideBias, int hasBias,
    int dstSel, long long strideCm, int ldc, int K)
{
    const int m  = blockIdx.z;
    const float* A = (useValA ? (const float*)g_val1 : Aext) + (long long)m*strideAm;
    const float* B = Bbase + (long long)m*strideBm;
    float* C = (dstSel==0 ? g_keyx : (dstSel==1 ? g_val1 : g_P)) + (long long)m*strideCm;

    const int i0 = blockIdx.y*128, j0 = blockIdx.x*128;
    __shared__ __align__(16) float As[8][128];
    __shared__ __align__(16) float Bs[8][128];
    const int tid = threadIdx.x;
    const int arow = tid>>1, acol = (tid&1)*4;
    const int tx = tid & 15, ty = tid >> 4;

    float acc[8][8];
    #pragma unroll
    for (int r=0;r<8;r++)
        #pragma unroll
        for (int c=0;c<8;c++) acc[r][c]=0.f;

    for (int kk=0; kk<K; kk+=8){
        float4 av = *(const float4*)(A + (long long)(i0+arow)*K + kk + acol);
        float4 bv = *(const float4*)(B + (long long)(j0+arow)*K + kk + acol);
        __syncthreads();
        As[acol+0][arow]=av.x; As[acol+1][arow]=av.y; As[acol+2][arow]=av.z; As[acol+3][arow]=av.w;
        Bs[acol+0][arow]=bv.x; Bs[acol+1][arow]=bv.y; Bs[acol+2][arow]=bv.z; Bs[acol+3][arow]=bv.w;
        __syncthreads();
        #pragma unroll
        for (int k=0;k<8;k++){
            float ar[8], br[8];
            *(float4*)&ar[0] = *(const float4*)&As[k][ty*8];
            *(float4*)&ar[4] = *(const float4*)&As[k][ty*8+4];
            *(float4*)&br[0] = *(const float4*)&Bs[k][tx*8];
            *(float4*)&br[4] = *(const float4*)&Bs[k][tx*8+4];
            #pragma unroll
            for (int r=0;r<8;r++)
                #pragma unroll
                for (int c=0;c<8;c++) acc[r][c] += ar[r]*br[c];
        }
    }
    #pragma unroll
    for (int r=0;r<8;r++){
        const int i = i0 + ty*8 + r;
        #pragma unroll
        for (int c=0;c<8;c++){
            const int j = j0 + tx*8 + c;
            float v = acc[r][c];
            if (hasBias) v += biasBase[(long long)m*strideBias + j];
            C[(long long)i*ldc + j] = v;
        }
    }
}

// ---------------- Pb[m,g] = bv[m]·W_ih[m,g,:];  Cb = b_ih + b_hh + Pb --------
__global__ __launch_bounds__(256) void k_pbcb(
    const float* __restrict__ bv, const float* __restrict__ Wih,
    const float* __restrict__ bih, const float* __restrict__ bhh)
{
    const int w = (blockIdx.x*blockDim.x + threadIdx.x) >> 5;
    const int lane = threadIdx.x & 31;
    if (w >= Mmod*Gg) return;
    const int m = w >> 11;
    const float* wrow = Wih + (long long)w*Dd;
    const float* bvr  = bv + (long long)m*Dd;
    float acc=0.f;
    #pragma unroll
    for (int i=0;i<4;i++){
        float4 a = *(const float4*)(wrow + (lane+32*i)*4);
        float4 b = *(const float4*)(bvr  + (lane+32*i)*4);
        acc += a.x*b.x + a.y*b.y + a.z*b.z + a.w*b.w;
    }
    #pragma unroll
    for (int off=16;off;off>>=1) acc += __shfl_down_sync(0xffffffffu, acc, off);
    if (lane==0){
        g_Pb[w] = acc;
        g_Cb[w] = acc + bih[w] + bhh[w];
    }
}

// ---------------- grid barrier ------------------------------------------------
__device__ __forceinline__ void gridbar(int& gen)
{
    __threadfence();
    __syncthreads();
    if (threadIdx.x == 0){
        if (atomicAdd(&g_barCnt, 1) == NB-1){
            atomicExch(&g_barCnt, 0);
            __threadfence();
            atomicAdd(&g_barGen, 1);
        } else {
            while (atomicAdd(&g_barGen, 0) == gen) __nanosleep(32);
        }
    }
    __syncthreads();
    gen++;
}

// ---------------- persistent step loop ---------------------------------------
__global__ __launch_bounds__(256,1) void k_loop(
    const float* __restrict__ Wq,  const float* __restrict__ bq,
    const float* __restrict__ bk,  const float* __restrict__ Whh,
    const float* __restrict__ Wqg, const float* __restrict__ Wkg,
    const float* __restrict__ Wvg,
    float* __restrict__ out, long long osz)
{
    __shared__ __align__(16) float hloc[Mmod*Hh];   // persistent local h (32KB)
    __shared__ __align__(16) float th[3][Hh];       // temp_h of needed active modules
    __shared__ float part[2][128];
    __shared__ float att0s[Mmod], att1s[Mmod];
    __shared__ float sl2[KACT*Mmod];
    __shared__ float att2s[KACT][Mmod];
    __shared__ int actFlag[Mmod], prevFlag[Mmod], actList[KACT];
    __shared__ int dirtyE[Mmod], dzList[Mmod];
    __shared__ int nLs, ndzS, needS[3], nNeedS, slotMap[Mmod];

    const int tid = threadIdx.x;
    const int lane = tid & 31, wid = tid >> 5;
    const int bx = blockIdx.x;
    const int gw = bx*8 + wid;
    int gen = 0;

    for (int i=tid;i<Mmod*Hh;i+=256) hloc[i]=0.f;
    if (tid<Mmod){ prevFlag[tid]=1; dzList[tid]=tid; }
    if (tid==0) ndzS = Mmod;
    __syncthreads();

    for (int t=0; t<Tlen; t++){
        // ============ region 1: z_hh/q GEMV for dirty modules (active at t-1) ===
        {
            const int rows = ndzS*2304;                 // 2048 z rows + 256 q rows / module
            const int per  = (rows + NB*8 - 1)/(NB*8);
            int r    = gw*per;
            int rend = r + per; if (rend > rows) rend = rows;
            while (r < rend){
                int nr = rend - r; if (nr > 4) nr = 4;
                const float* wr[4]; const float* hv[4]; float* dst[4]; float bias[4];
                #pragma unroll
                for (int j=0;j<4;j++){
                    int rr = r + (j < nr ? j : 0);
                    int im = rr/2304;
                    int m  = dzList[im];
                    int k  = rr - im*2304;
                    if (k < Gg){
                        wr[j]  = Whh + ((long long)m*Gg + k)*Hh;
                        dst[j] = &g_zhh[m*Gg + k];
                        bias[j]= 0.f;
                    } else {
                        int kk = k - Gg;
                        wr[j]  = Wq + ((long long)m*QKd + kk)*Hh;
                        dst[j] = &g_qbuf[m*QKd + kk];
                        bias[j]= bq[m*QKd + kk];
                    }
                    hv[j] = &hloc[m*Hh];
                }
                float4 a[4][4];
                #pragma unroll
                for (int j=0;j<4;j++)
                    #pragma unroll
                    for (int i=0;i<4;i++)
                        a[j][i] = *(const float4*)(wr[j] + (lane+32*i)*4);
                float acc[4] = {0.f,0.f,0.f,0.f};
                #pragma unroll
                for (int j=0;j<4;j++)
                    #pragma unroll
                    for (int i=0;i<4;i++){
                        float4 b = *(const float4*)(hv[j] + (lane+32*i)*4);
                        acc[j] += a[j][i].x*b.x + a[j][i].y*b.y + a[j][i].z*b.z + a[j][i].w*b.w;
                    }
                #pragma unroll
                for (int j=0;j<4;j++){
                    float v = acc[j];
                    #pragma unroll
                    for (int off=16;off;off>>=1) v += __shfl_down_sync(0xffffffffu, v, off);
                    if (lane==0 && j < nr) *dst[j] = v + bias[j];
                }
                r += nr;
            }
        }
        gridbar(gen);

        // ============ region 2: att (redundant) + D (as needed) + E slice =======
        // att: warp w handles modules w and w+8
        #pragma unroll
        for (int rep=0; rep<2; rep++){
            const int m = wid + rep*8;
            const float* qb  = g_qbuf + m*QKd + lane*8;
            float4 q1  = __ldcg((const float4*)qb);
            float4 q2v = __ldcg((const float4*)(qb+4));
            const float* bkp = bk + m*QKd + lane*8;
            float4 b1 = *(const float4*)bkp;
            float4 b2 = *(const float4*)(bkp+4);
            const float* kx = g_keyx + ((long long)t*Mmod + m)*QKd + lane*8;
            float4 k1  = *(const float4*)kx;
            float4 k2v = *(const float4*)(kx+4);
            float p0 = q1.x*b1.x + q1.y*b1.y + q1.z*b1.z + q1.w*b1.w
                     + q2v.x*b2.x + q2v.y*b2.y + q2v.z*b2.z + q2v.w*b2.w;
            float p1 = q1.x*k1.x + q1.y*k1.y + q1.z*k1.z + q1.w*k1.w
                     + q2v.x*k2v.x + q2v.y*k2v.y + q2v.z*k2v.z + q2v.w*k2v.w;
            #pragma unroll
            for (int off=16;off;off>>=1){
                p0 += __shfl_down_sync(0xffffffffu,p0,off);
                p1 += __shfl_down_sync(0xffffffffu,p1,off);
            }
            if (lane==0){
                const float scale = 0.0625f;        /* 1/sqrt(256) */
                float l0 = p0*scale, l1 = p1*scale;
                float mx = fmaxf(l0,l1);
                float e0 = expf(l0-mx), e1 = expf(l1-mx);
                float s = e0+e1;
                att0s[m] = e0/s;
                att1s[m] = e1/s;
            }
        }
        __syncthreads();
        if (tid < Mmod){
            const float my0 = att0s[tid];
            int cnt=0;
            #pragma unroll
            for (int q=0;q<Mmod;q++) cnt += (att0s[q] < my0) || (att0s[q]==my0 && q<tid);
            actFlag[tid] = (cnt < KACT);
        }
        __syncthreads();
        if (tid==0){
            int na=0;
            for (int m=0;m<Mmod;m++) if (actFlag[m]) actList[na++]=m;
            int n=0;
            for (int m=0;m<Mmod;m++) if (actFlag[m] | prevFlag[m]) dirtyE[n++]=m;
            nLs = n;
            const int total = n*1536;
            const int per = (total + NB - 1)/NB;
            int s0 = bx*per, s1 = s0+per; if (s1>total) s1=total;
            int nn=0;
            if (s1 > s0){
                int mi0 = s0/1536, mi1 = (s1-1)/1536;
                for (int mi=mi0; mi<=mi1; mi++){
                    int mm = dirtyE[mi];
                    if (actFlag[mm]) needS[nn++] = mm;
                }
            }
            if (bx < Mmod && actFlag[bx]){
                bool have=false;
                for (int s=0;s<nn;s++) if (needS[s]==bx) have=true;
                if (!have) needS[nn++] = bx;
            }
            nNeedS = nn;
            for (int s=0;s<nn;s++) slotMap[needS[s]] = s;
        }
        // top-k index output (block 0)
        if (bx==0 && tid==0 && osz >= (long long)Tlen*Mmod*Hh + (long long)Tlen*KACT){
            bool used[Mmod];
            #pragma unroll
            for (int q=0;q<Mmod;q++) used[q]=false;
            for (int r2=0;r2<KACT;r2++){
                float best = 3.4e38f; int bi=0;
                for (int q=0;q<Mmod;q++)
                    if (!used[q] && att0s[q] < best){ best=att0s[q]; bi=q; }
                used[bi]=true;
                out[(long long)Tlen*Mmod*Hh + (long long)t*KACT + r2] = (float)bi;
            }
        }
        __syncthreads();

        // D (gates/LSTM) for the active modules this block needs
        for (int s=0; s<nNeedS; s++){
            const int m = needS[s];
            const float att1 = att1s[m];
            const float* Cbp = g_Cb + m*Gg;
            const float* Pbp = g_Pb + m*Gg;
            const float* Pp  = g_P + (long long)t*Mmod*Gg + (long long)m*Gg;
            const float* zp  = g_zhh + m*Gg;
            const bool writer = (bx == m);
            const int rb = (t&1)*Mmod*Hh, wb = ((t+1)&1)*Mmod*Hh;
            for (int jj=tid; jj<Hh; jj+=256){
                float gv[4];
                #pragma unroll
                for (int q=0;q<4;q++){
                    const int g = jj + q*Hh;
                    gv[q] = Cbp[g] + att1*(__ldg(&Pp[g]) - Pbp[g]) + __ldcg(&zp[g]);
                }
                const float ig = 1.f/(1.f+expf(-gv[0]));
                const float fg = 1.f/(1.f+expf(-gv[1]));
                const float gg = tanhf(gv[2]);
                const float og = 1.f/(1.f+expf(-gv[3]));
                const float c_old = __ldcg(&g_cbuf[rb + m*Hh + jj]);
                const float cn = fg*c_old + ig*gg;
                const float hn = og*tanhf(cn);
                th[s][jj] = hn;
                if (writer){
                    g_cbuf[wb + m*Hh + jj] = cn;
                    g_temph[m*Hh + jj] = hn;
                }
            }
        }
        if (bx < Mmod && !actFlag[bx]){
            const int wb = ((t+1)&1)*Mmod*Hh;
            for (int jj=tid; jj<Hh; jj+=256) g_cbuf[wb + bx*Hh + jj] = 0.f;
        }
        __syncthreads();

        // E: q2/k2/v2 columns for dirtyE modules (split-K=2 per output)
        {
            const int total = nLs*1536;
            const int per = (total + NB - 1)/NB;
            int s0 = bx*per, s1 = s0+per; if (s1>total) s1=total;
            for (int base=s0; base<s1; base+=128){
                int cnt = s1-base; if (cnt>128) cnt=128;
                const int kp = tid >> 7;       // 0/1
                const int ol = tid & 127;
                float val = 0.f;
                if (ol < cnt){
                    const int u = base + ol;
                    const int mi = u/1536;
                    const int m  = dirtyE[mi];
                    const int rem = u - mi*1536;
                    const int mat = rem >> 9;
                    const int o   = rem & 511;
                    const float* Wsel = (mat==0 ? Wqg : (mat==1 ? Wkg : Wvg));
                    const float* Wc = Wsel + (long long)m*Hh*Hh + (long long)(kp<<8)*Hh + o;
                    const float* tv = actFlag[m] ? th[slotMap[m]] : &hloc[m*Hh];
                    const int hb = kp<<8;
                    float acc = 0.f;
                    for (int h=0; h<256; h+=16){
                        #pragma unroll
                        for (int u2=0; u2<16; u2++)
                            acc += tv[hb + h + u2] * Wc[(h+u2)*Hh];
                    }
                    val = acc;
                }
                __syncthreads();
                part[kp][ol] = val;
                __syncthreads();
                if (tid < cnt){
                    const int u = base + tid;
                    const int mi = u/1536;
                    const int m  = dirtyE[mi];
                    const int rem = u - mi*1536;
                    const int mat = rem >> 9;
                    const int o   = rem & 511;
                    float* dst = (mat==0 ? g_q2 : (mat==1 ? g_k2 : g_v2));
                    dst[m*Hh + o] = part[0][tid] + part[1][tid];
                }
            }
        }
        gridbar(gen);

        // ============ region 3: F (redundant per block) + h update + output =====
        // 64 dots: (active a) x (all b); warp w handles 8 pairs
        for (int p = wid*8; p < wid*8+8; p++){
            const int ai = p >> 4;
            const int b2 = p & 15;
            const float* q2p = g_q2 + actList[ai]*Hh;
            const float* kp2 = g_k2 + b2*Hh;
            float acc=0.f;
            #pragma unroll
            for (int i=0;i<4;i++){
                float4 kv4 = __ldcg((const float4*)(kp2 + (lane+32*i)*4));
                float4 qv4 = __ldcg((const float4*)(q2p + (lane+32*i)*4));
                acc += kv4.x*qv4.x + kv4.y*qv4.y + kv4.z*qv4.z + kv4.w*qv4.w;
            }
            #pragma unroll
            for (int off=16;off;off>>=1) acc += __shfl_down_sync(0xffffffffu, acc, off);
            if (lane==0) sl2[p] = acc;
        }
        __syncthreads();
        if (tid < KACT){
            float mx=-3.4e38f;
            for (int q=0;q<Mmod;q++) mx = fmaxf(mx, sl2[tid*Mmod+q]);
            float s=0.f;
            for (int q=0;q<Mmod;q++){ float e=expf(sl2[tid*Mmod+q]-mx); att2s[tid][q]=e; s+=e; }
            const float inv = 1.f/s;
            for (int q=0;q<Mmod;q++) att2s[tid][q]*=inv;
        }
        __syncthreads();
        #pragma unroll
        for (int i=0;i<KACT;i++){
            const int a = actList[i];
            for (int o=tid;o<Hh;o+=256){
                float s=0.f;
                #pragma unroll
                for (int q=0;q<Mmod;q++) s += att2s[i][q]*__ldcg(&g_v2[q*Hh+o]);
                hloc[a*Hh+o] = s + __ldcg(&g_temph[a*Hh+o]);
            }
        }
        __syncthreads();
        if (bx < Mmod){
            for (int o=tid;o<Hh;o+=256)
                out[((long long)t*Mmod + bx)*Hh + o] = hloc[bx*Hh + o];
        }
        if (tid < Mmod) prevFlag[tid] = actFlag[tid];
        __syncthreads();
        if (tid==0){
            int n=0;
            for (int m=0;m<Mmod;m++) if (prevFlag[m]) dzList[n++]=m;
            ndzS = n;
        }
        __syncthreads();
        // no grid barrier needed here: region 1 of t+1 writes only zhh/qbuf,
        // which region 3 of step t never reads; barrier 1 of t+1 gates region 2.
    }
}

// ---------------- launch ------------------------------------------------------
extern "C" void kernel_launch(void* const* d_in, const int* in_sizes, int n_in,
                              void* d_out, int out_size)
{
    const float* inputs = (const float*)d_in[0];
    const float* Wq   = (const float*)d_in[1];
    const float* bq   = (const float*)d_in[2];
    const float* Wk   = (const float*)d_in[3];
    const float* bk   = (const float*)d_in[4];
    const float* Wv   = (const float*)d_in[5];
    const float* bv   = (const float*)d_in[6];
    const float* Wih  = (const float*)d_in[7];
    const float* bih  = (const float*)d_in[8];
    const float* Whh  = (const float*)d_in[9];
    const float* bhh  = (const float*)d_in[10];
    const float* Wqg  = (const float*)d_in[11];
    const float* Wkg  = (const float*)d_in[12];
    const float* Wvg  = (const float*)d_in[13];
    float* out = (float*)d_out;
    const long long osz = (long long)out_size;

    k_init<<<1024,256>>>(out, osz);

    // key_x[t,m,k] = x_t @ Wk^T + bk
    {
        dim3 g(QKd/128, Tlen/128, Mmod);
        sgemm128<<<g,256>>>(inputs, 0, (long long)Tlen*Dd,
                            Wk, (long long)QKd*Dd,
                            bk, QKd, 1,
                            0, (long long)QKd, Mmod*QKd, Dd);
    }
    // val1[m,t,v] = x_t @ Wv^T + bv
    {
        dim3 g(Dd/128, Tlen/128, Mmod);
        sgemm128<<<g,256>>>(inputs, 0, (long long)Tlen*Dd,
                            Wv, (long long)Dd*Dd,
                            bv, Dd, 1,
                            1, (long long)Tlen*Dd, Dd, Dd);
    }
    k_pbcb<<<(Mmod*Gg)/8, 256>>>(bv, Wih, bih, bhh);
    // P[t,m,g] = val1 @ W_ih^T
    {
        dim3 g(Gg/128, Tlen/128, Mmod);
        sgemm128<<<g,256>>>(nullptr, 1, (long long)Tlen*Dd,
                            Wih, (long long)Gg*Dd,
                            nullptr, 0, 0,
                            2, (long long)Gg, Mmod*Gg, Dd);
    }

    k_loop<<<NB,256>>>(Wq, bq, bk, Whh, Wqg, Wkg, Wvg, out, osz);
}

// round 9
// speedup vs baseline: 1.8940x; 1.1046x over previous
#include <cuda_runtime.h>
#include <math.h>

#define Mmod 16
#define Tlen 512
#define Dd   512
#define Hh   512
#define QKd  256
#define Gg   2048   /* 4*H */
#define KACT 4
#define NB   148    /* persistent blocks; <= SM count, 1 block/SM guaranteed */

// ---------------- scratch (device globals; no allocation allowed) ------------
__device__ float g_keyx[Tlen*Mmod*QKd];   // [t][m][k]          8 MB
__device__ float g_val1[Mmod*Tlen*Dd];    // [m][t][d]         16 MB
__device__ float g_P[Tlen*Mmod*Gg];       // [t][m][g]         64 MB
__device__ float g_WgT[3*Mmod*Hh*Hh];     // [mat][m][o][h]    48 MB (transposed gate weights)
__device__ float g_Pb[Mmod*Gg];
__device__ float g_Cb[Mmod*Gg];
__device__ float g_cbuf[2*Mmod*Hh];       // double-buffered c
__device__ float g_zhh[Mmod*Gg];
__device__ float g_qbuf[Mmod*QKd];
__device__ float g_q2[Mmod*Hh];
__device__ float g_k2[Mmod*Hh];
__device__ float g_v2[Mmod*Hh];
__device__ int   g_barCnt;
__device__ unsigned g_barGen;

// ---------------- init ---------------------------------------------------------
__global__ void k_init(float* __restrict__ out, long long out_size,
                       const float* __restrict__ bq)
{
    long long i = (long long)blockIdx.x*blockDim.x + threadIdx.x;
    long long stride = (long long)gridDim.x*blockDim.x;
    for (long long j=i; j<out_size; j+=stride) out[j]=0.f;
    for (long long j=i; j<2*Mmod*Hh; j+=stride) g_cbuf[j]=0.f;
    for (long long j=i; j<Mmod*Gg; j+=stride)  g_zhh[j]=0.f;     // h0=0 -> zhh=0
    for (long long j=i; j<Mmod*QKd; j+=stride) g_qbuf[j]=bq[j];  // h0=0 -> q=bq
    for (long long j=i; j<Mmod*Hh; j+=stride){ g_k2[j]=0.f; g_v2[j]=0.f; g_q2[j]=0.f; }
    if (i==0){ g_barCnt=0; g_barGen=0u; }
}

// ---------------- transpose gate weights: WgT[mat][m][o][h] = W[m][h][o] -----
__global__ __launch_bounds__(256) void k_transp(
    const float* __restrict__ Wqg, const float* __restrict__ Wkg,
    const float* __restrict__ Wvg)
{
    __shared__ float tile[32][33];
    const int mm = blockIdx.z;               // mat*16+m, 0..47
    const int mat = mm >> 4, m = mm & 15;
    const float* W = (mat==0?Wqg:(mat==1?Wkg:Wvg)) + (long long)m*Hh*Hh;
    const int o0 = blockIdx.x*32, h0 = blockIdx.y*32;
    const int tx = threadIdx.x & 31, ty = threadIdx.x >> 5;   // 32x8
    for (int i=ty;i<32;i+=8)
        tile[i][tx] = W[(long long)(h0+i)*Hh + o0+tx];
    __syncthreads();
    float* dstb = g_WgT + ((long long)mm*Hh + o0)*Hh + h0;
    for (int i=ty;i<32;i+=8)
        dstb[(long long)i*Hh + tx] = tile[tx][i];
}

// ---------------- fp32 SGEMM: C[i,j] = sum_k A[i,k]*B[j,k] (+bias[j]) --------
__global__ __launch_bounds__(256) void sgemm128(
    const float* __restrict__ Aext, int useValA, long long strideAm,
    const float* __restrict__ Bbase, long long strideBm,
    const float* __restrict__ biasBase, int strideBias, int hasBias,
    int dstSel, long long strideCm, int ldc, int K)
{
    const int m  = blockIdx.z;
    const float* A = (useValA ? (const float*)g_val1 : Aext) + (long long)m*strideAm;
    const float* B = Bbase + (long long)m*strideBm;
    float* C = (dstSel==0 ? g_keyx : (dstSel==1 ? g_val1 : g_P)) + (long long)m*strideCm;

    const int i0 = blockIdx.y*128, j0 = blockIdx.x*128;
    __shared__ __align__(16) float As[8][128];
    __shared__ __align__(16) float Bs[8][128];
    const int tid = threadIdx.x;
    const int arow = tid>>1, acol = (tid&1)*4;
    const int tx = tid & 15, ty = tid >> 4;

    float acc[8][8];
    #pragma unroll
    for (int r=0;r<8;r++)
        #pragma unroll
        for (int c=0;c<8;c++) acc[r][c]=0.f;

    for (int kk=0; kk<K; kk+=8){
        float4 av = *(const float4*)(A + (long long)(i0+arow)*K + kk + acol);
        float4 bv = *(const float4*)(B + (long long)(j0+arow)*K + kk + acol);
        __syncthreads();
        As[acol+0][arow]=av.x; As[acol+1][arow]=av.y; As[acol+2][arow]=av.z; As[acol+3][arow]=av.w;
        Bs[acol+0][arow]=bv.x; Bs[acol+1][arow]=bv.y; Bs[acol+2][arow]=bv.z; Bs[acol+3][arow]=bv.w;
        __syncthreads();
        #pragma unroll
        for (int k=0;k<8;k++){
            float ar[8], br[8];
            *(float4*)&ar[0] = *(const float4*)&As[k][ty*8];
            *(float4*)&ar[4] = *(const float4*)&As[k][ty*8+4];
            *(float4*)&br[0] = *(const float4*)&Bs[k][tx*8];
            *(float4*)&br[4] = *(const float4*)&Bs[k][tx*8+4];
            #pragma unroll
            for (int r=0;r<8;r++)
                #pragma unroll
                for (int c=0;c<8;c++) acc[r][c] += ar[r]*br[c];
        }
    }
    #pragma unroll
    for (int r=0;r<8;r++){
        const int i = i0 + ty*8 + r;
        #pragma unroll
        for (int c=0;c<8;c++){
            const int j = j0 + tx*8 + c;
            float v = acc[r][c];
            if (hasBias) v += biasBase[(long long)m*strideBias + j];
            C[(long long)i*ldc + j] = v;
        }
    }
}

// ---------------- Pb[m,g] = bv[m]·W_ih[m,g,:];  Cb = b_ih + b_hh + Pb --------
__global__ __launch_bounds__(256) void k_pbcb(
    const float* __restrict__ bv, const float* __restrict__ Wih,
    const float* __restrict__ bih, const float* __restrict__ bhh)
{
    const int w = (blockIdx.x*blockDim.x + threadIdx.x) >> 5;
    const int lane = threadIdx.x & 31;
    if (w >= Mmod*Gg) return;
    const int m = w >> 11;
    const float* wrow = Wih + (long long)w*Dd;
    const float* bvr  = bv + (long long)m*Dd;
    float acc=0.f;
    #pragma unroll
    for (int i=0;i<4;i++){
        float4 a = *(const float4*)(wrow + (lane+32*i)*4);
        float4 b = *(const float4*)(bvr  + (lane+32*i)*4);
        acc += a.x*b.x + a.y*b.y + a.z*b.z + a.w*b.w;
    }
    #pragma unroll
    for (int off=16;off;off>>=1) acc += __shfl_down_sync(0xffffffffu, acc, off);
    if (lane==0){
        g_Pb[w] = acc;
        g_Cb[w] = acc + bih[w] + bhh[w];
    }
}

// ---------------- grid barrier (acquire-load polling) -------------------------
__device__ __forceinline__ void gridbar(unsigned& gen)
{
    __threadfence();
    __syncthreads();
    if (threadIdx.x == 0){
        if (atomicAdd(&g_barCnt, 1) == NB-1){
            atomicExch(&g_barCnt, 0);
            __threadfence();
            atomicAdd(&g_barGen, 1u);
        } else {
            unsigned v;
            do {
                __nanosleep(20);
                asm volatile("ld.acquire.gpu.u32 %0, [%1];" : "=r"(v) : "l"(&g_barGen));
            } while (v == gen);
        }
    }
    __syncthreads();
    gen++;
}

// ---------------- persistent step loop ---------------------------------------
__global__ __launch_bounds__(256,1) void k_loop(
    const float* __restrict__ Wq,  const float* __restrict__ bq,
    const float* __restrict__ bk,  const float* __restrict__ Whh,
    float* __restrict__ out, long long osz)
{
    __shared__ __align__(16) float hloc[Mmod*Hh];   // persistent local h (32KB)
    __shared__ __align__(16) float th[KACT][Hh];    // temp_h of active modules (8KB)
    __shared__ float att0s[Mmod], att1s[Mmod];
    __shared__ float sl2[KACT*Mmod];
    __shared__ float att2s[KACT][Mmod];
    __shared__ int actFlag[Mmod], prevFlag[Mmod];
    __shared__ int actList[KACT], dirtyL[Mmod], slotOf[Mmod];
    __shared__ int nDirtyS;

    const int tid = threadIdx.x;
    const int lane = tid & 31, wid = tid >> 5;
    const int bx = blockIdx.x;
    const int gw = bx*8 + wid;
    unsigned gen = 0;

    for (int i=tid;i<Mmod*Hh;i+=256) hloc[i]=0.f;
    if (tid<Mmod) prevFlag[tid]=0;
    __syncthreads();

    for (int t=0; t<Tlen; t++){
        // ======= region 1: z_hh/q GEMV for modules active at t-1 (h changed) ====
        if (t > 0){
            const int rows = KACT*2304;                 // 2048 z rows + 256 q rows / module
            const int per  = (rows + NB*8 - 1)/(NB*8);  // 8
            int r    = gw*per;
            int rend = r + per; if (rend > rows) rend = rows;
            while (r < rend){
                int nr = rend - r; if (nr > 4) nr = 4;
                const float* wr[4]; const float* hv[4]; float* dst[4]; float bias[4];
                #pragma unroll
                for (int j=0;j<4;j++){
                    int rr = r + (j < nr ? j : 0);
                    int im = rr/2304;
                    int m  = actList[im];               // act(t-1)
                    int k  = rr - im*2304;
                    if (k < Gg){
                        wr[j]  = Whh + ((long long)m*Gg + k)*Hh;
                        dst[j] = &g_zhh[m*Gg + k];
                        bias[j]= 0.f;
                    } else {
                        int kk = k - Gg;
                        wr[j]  = Wq + ((long long)m*QKd + kk)*Hh;
                        dst[j] = &g_qbuf[m*QKd + kk];
                        bias[j]= bq[m*QKd + kk];
                    }
                    hv[j] = &hloc[m*Hh];
                }
                float4 a[4][4];
                #pragma unroll
                for (int j=0;j<4;j++)
                    #pragma unroll
                    for (int i=0;i<4;i++)
                        a[j][i] = *(const float4*)(wr[j] + (lane+32*i)*4);
                float acc[4] = {0.f,0.f,0.f,0.f};
                #pragma unroll
                for (int j=0;j<4;j++)
                    #pragma unroll
                    for (int i=0;i<4;i++){
                        float4 b = *(const float4*)(hv[j] + (lane+32*i)*4);
                        acc[j] += a[j][i].x*b.x + a[j][i].y*b.y + a[j][i].z*b.z + a[j][i].w*b.w;
                    }
                #pragma unroll
                for (int j=0;j<4;j++){
                    float v = acc[j];
                    #pragma unroll
                    for (int off=16;off;off>>=1) v += __shfl_down_sync(0xffffffffu, v, off);
                    if (lane==0 && j < nr) *dst[j] = v + bias[j];
                }
                r += nr;
            }
        }
        gridbar(gen);

        // ======= region 2: att (redundant) + D (redundant) + E (spread) =========
        // att: warp w handles modules w and w+8
        #pragma unroll
        for (int rep=0; rep<2; rep++){
            const int m = wid + rep*8;
            const float* qb  = g_qbuf + m*QKd + lane*8;
            float4 q1  = __ldcg((const float4*)qb);
            float4 q2v = __ldcg((const float4*)(qb+4));
            const float* bkp = bk + m*QKd + lane*8;
            float4 b1 = *(const float4*)bkp;
            float4 b2 = *(const float4*)(bkp+4);
            const float* kx = g_keyx + ((long long)t*Mmod + m)*QKd + lane*8;
            float4 k1  = *(const float4*)kx;
            float4 k2v = *(const float4*)(kx+4);
            float p0 = q1.x*b1.x + q1.y*b1.y + q1.z*b1.z + q1.w*b1.w
                     + q2v.x*b2.x + q2v.y*b2.y + q2v.z*b2.z + q2v.w*b2.w;
            float p1 = q1.x*k1.x + q1.y*k1.y + q1.z*k1.z + q1.w*k1.w
                     + q2v.x*k2v.x + q2v.y*k2v.y + q2v.z*k2v.z + q2v.w*k2v.w;
            #pragma unroll
            for (int off=16;off;off>>=1){
                p0 += __shfl_down_sync(0xffffffffu,p0,off);
                p1 += __shfl_down_sync(0xffffffffu,p1,off);
            }
            if (lane==0){
                const float scale = 0.0625f;        /* 1/sqrt(256) */
                float l0 = p0*scale, l1 = p1*scale;
                float mx = fmaxf(l0,l1);
                float e0 = expf(l0-mx), e1 = expf(l1-mx);
                float s = e0+e1;
                att0s[m] = e0/s;
                att1s[m] = e1/s;
            }
        }
        __syncthreads();
        if (tid < Mmod){
            const float my0 = att0s[tid];
            int cnt=0;
            #pragma unroll
            for (int q=0;q<Mmod;q++) cnt += (att0s[q] < my0) || (att0s[q]==my0 && q<tid);
            actFlag[tid] = (cnt < KACT);
        }
        __syncthreads();
        if (tid==0){
            int na=0, n=0;
            for (int m=0;m<Mmod;m++){
                if (actFlag[m]){ slotOf[m]=na; actList[na++]=m; }
                if (actFlag[m] | prevFlag[m]) dirtyL[n++]=m;
            }
            nDirtyS = n;
        }
        // top-k index output (block 0)
        if (bx==0 && tid==32 && osz >= (long long)Tlen*Mmod*Hh + (long long)Tlen*KACT){
            bool used[Mmod];
            #pragma unroll
            for (int q=0;q<Mmod;q++) used[q]=false;
            for (int r2=0;r2<KACT;r2++){
                float best = 3.4e38f; int bi=0;
                for (int q=0;q<Mmod;q++)
                    if (!used[q] && att0s[q] < best){ best=att0s[q]; bi=q; }
                used[bi]=true;
                out[(long long)Tlen*Mmod*Hh + (long long)t*KACT + r2] = (float)bi;
            }
        }
        __syncthreads();

        // D (gates/LSTM) redundant for the 4 active modules
        {
            const int rb = (t&1)*Mmod*Hh, wb = ((t+1)&1)*Mmod*Hh;
            #pragma unroll
            for (int s=0; s<KACT; s++){
                const int m = actList[s];
                const float att1 = att1s[m];
                const float* Cbp = g_Cb + m*Gg;
                const float* Pbp = g_Pb + m*Gg;
                const float* Pp  = g_P + (long long)t*Mmod*Gg + (long long)m*Gg;
                const float* zp  = g_zhh + m*Gg;
                const bool writer = (bx == m);
                #pragma unroll
                for (int it=0; it<2; it++){
                    const int jj = tid + it*256;
                    float gv[4];
                    #pragma unroll
                    for (int q=0;q<4;q++){
                        const int g = jj + q*Hh;
                        gv[q] = Cbp[g] + att1*(__ldg(&Pp[g]) - Pbp[g]) + __ldcg(&zp[g]);
                    }
                    const float ig = 1.f/(1.f+expf(-gv[0]));
                    const float fg = 1.f/(1.f+expf(-gv[1]));
                    const float gg = tanhf(gv[2]);
                    const float og = 1.f/(1.f+expf(-gv[3]));
                    const float c_old = __ldcg(&g_cbuf[rb + m*Hh + jj]);
                    const float cn = fg*c_old + ig*gg;
                    const float hn = og*tanhf(cn);
                    th[s][jj] = hn;
                    if (writer) g_cbuf[wb + m*Hh + jj] = cn;
                }
            }
            if (bx < Mmod && !actFlag[bx]){
                #pragma unroll
                for (int it=0; it<2; it++)
                    g_cbuf[wb + bx*Hh + tid + it*256] = 0.f;
            }
        }
        __syncthreads();

        // E: q2 (active) + k2/v2 (dirty) GEMV over transposed WgT, warp-spread
        {
            const int totalE = KACT*Hh + nDirtyS*2*Hh;     // 2048 + nDirty*1024
            const int per = (totalE + NB*8 - 1)/(NB*8);
            int r    = gw*per;
            int rend = r + per; if (rend > totalE) rend = totalE;
            while (r < rend){
                int nr = rend - r; if (nr > 4) nr = 4;
                const float* wr[4]; const float* tv[4]; float* dst[4];
                #pragma unroll
                for (int j=0;j<4;j++){
                    int rr = r + (j < nr ? j : 0);
                    if (rr < KACT*Hh){
                        int s = rr >> 9, o = rr & 511;
                        int m = actList[s];
                        wr[j]  = g_WgT + ((long long)m*Hh + o)*Hh;           // mat 0
                        tv[j]  = th[s];
                        dst[j] = &g_q2[m*Hh + o];
                    } else {
                        int v = rr - KACT*Hh;
                        int mi = v >> 10;
                        int m  = dirtyL[mi];
                        int rm = v & 1023;
                        int mat = 1 + (rm >> 9);
                        int o  = rm & 511;
                        wr[j]  = g_WgT + (((long long)mat*Mmod + m)*Hh + o)*Hh;
                        tv[j]  = actFlag[m] ? th[slotOf[m]] : &hloc[m*Hh];
                        dst[j] = (mat==1 ? g_k2 : g_v2) + m*Hh + o;
                    }
                }
                float4 a[4][4];
                #pragma unroll
                for (int j=0;j<4;j++)
                    #pragma unroll
                    for (int i=0;i<4;i++)
                        a[j][i] = *(const float4*)(wr[j] + (lane+32*i)*4);
                float acc[4] = {0.f,0.f,0.f,0.f};
                #pragma unroll
                for (int j=0;j<4;j++)
                    #pragma unroll
                    for (int i=0;i<4;i++){
                        float4 b = *(const float4*)(tv[j] + (lane+32*i)*4);
                        acc[j] += a[j][i].x*b.x + a[j][i].y*b.y + a[j][i].z*b.z + a[j][i].w*b.w;
                    }
                #pragma unroll
                for (int j=0;j<4;j++){
                    float v = acc[j];
                    #pragma unroll
                    for (int off=16;off;off>>=1) v += __shfl_down_sync(0xffffffffu, v, off);
                    if (lane==0 && j < nr) *dst[j] = v;
                }
                r += nr;
            }
        }
        gridbar(gen);

        // ======= region 3: F (redundant) + h update + output =====================
        for (int p = wid*8; p < wid*8+8; p++){
            const int ai = p >> 4;
            const int b2 = p & 15;
            const float* q2p = g_q2 + actList[ai]*Hh;
            const float* kp2 = g_k2 + b2*Hh;
            float acc=0.f;
            #pragma unroll
            for (int i=0;i<4;i++){
                float4 kv4 = __ldcg((const float4*)(kp2 + (lane+32*i)*4));
                float4 qv4 = __ldcg((const float4*)(q2p + (lane+32*i)*4));
                acc += kv4.x*qv4.x + kv4.y*qv4.y + kv4.z*qv4.z + kv4.w*qv4.w;
            }
            #pragma unroll
            for (int off=16;off;off>>=1) acc += __shfl_down_sync(0xffffffffu, acc, off);
            if (lane==0) sl2[p] = acc;
        }
        __syncthreads();
        if (tid < KACT){
            float mx=-3.4e38f;
            for (int q=0;q<Mmod;q++) mx = fmaxf(mx, sl2[tid*Mmod+q]);
            float s=0.f;
            for (int q=0;q<Mmod;q++){ float e=expf(sl2[tid*Mmod+q]-mx); att2s[tid][q]=e; s+=e; }
            const float inv = 1.f/s;
            for (int q=0;q<Mmod;q++) att2s[tid][q]*=inv;
        }
        __syncthreads();
        #pragma unroll
        for (int i=0;i<KACT;i++){
            const int a = actList[i];
            #pragma unroll
            for (int it=0; it<2; it++){
                const int o = tid + it*256;
                float s=0.f;
                #pragma unroll
                for (int q=0;q<Mmod;q++) s += att2s[i][q]*__ldcg(&g_v2[q*Hh+o]);
                hloc[a*Hh+o] = s + th[i][o];
            }
        }
        __syncthreads();
        if (bx < Mmod){
            #pragma unroll
            for (int it=0; it<2; it++){
                const int o = tid + it*256;
                out[((long long)t*Mmod + bx)*Hh + o] = hloc[bx*Hh + o];
            }
        }
        if (tid < Mmod) prevFlag[tid] = actFlag[tid];
        __syncthreads();
        // no grid barrier here: region 1 of t+1 writes only zhh/qbuf,
        // never read in region 3; bar1 of t+1 gates region 2.
    }
}

// ---------------- launch ------------------------------------------------------
extern "C" void kernel_launch(void* const* d_in, const int* in_sizes, int n_in,
                              void* d_out, int out_size)
{
    const float* inputs = (const float*)d_in[0];
    const float* Wq   = (const float*)d_in[1];
    const float* bq   = (const float*)d_in[2];
    const float* Wk   = (const float*)d_in[3];
    const float* bk   = (const float*)d_in[4];
    const float* Wv   = (const float*)d_in[5];
    const float* bv   = (const float*)d_in[6];
    const float* Wih  = (const float*)d_in[7];
    const float* bih  = (const float*)d_in[8];
    const float* Whh  = (const float*)d_in[9];
    const float* bhh  = (const float*)d_in[10];
    const float* Wqg  = (const float*)d_in[11];
    const float* Wkg  = (const float*)d_in[12];
    const float* Wvg  = (const float*)d_in[13];
    float* out = (float*)d_out;
    const long long osz = (long long)out_size;

    k_init<<<1024,256>>>(out, osz, bq);

    {   // transpose gate weights once
        dim3 g(16,16,48);
        k_transp<<<g,256>>>(Wqg, Wkg, Wvg);
    }
    // key_x[t,m,k] = x_t @ Wk^T + bk
    {
        dim3 g(QKd/128, Tlen/128, Mmod);
        sgemm128<<<g,256>>>(inputs, 0, (long long)Tlen*Dd,
                            Wk, (long long)QKd*Dd,
                            bk, QKd, 1,
                            0, (long long)QKd, Mmod*QKd, Dd);
    }
    // val1[m,t,v] = x_t @ Wv^T + bv
    {
        dim3 g(Dd/128, Tlen/128, Mmod);
        sgemm128<<<g,256>>>(inputs, 0, (long long)Tlen*Dd,
                            Wv, (long long)Dd*Dd,
                            bv, Dd, 1,
                            1, (long long)Tlen*Dd, Dd, Dd);
    }
    k_pbcb<<<(Mmod*Gg)/8, 256>>>(bv, Wih, bih, bhh);
    // P[t,m,g] = val1 @ W_ih^T
    {
        dim3 g(Gg/128, Tlen/128, Mmod);
        sgemm128<<<g,256>>>(nullptr, 1, (long long)Tlen*Dd,
                            Wih, (long long)Gg*Dd,
                            nullptr, 0, 0,
                            2, (long long)Gg, Mmod*Gg, Dd);
    }

    k_loop<<<NB,256>>>(Wq, bq, bk, Whh, out, osz);
}

// round 10
// speedup vs baseline: 2.4922x; 1.3159x over previous
#include <cuda_runtime.h>
#include <math.h>

#define Mmod 16
#define Tlen 512
#define Dd   512
#define Hh   512
#define QKd  256
#define Gg   2048   /* 4*H */
#define KACT 4
#define NB   148    /* persistent blocks; <= SM count, 1 block/SM guaranteed */
#define NT   512    /* threads per block in k_loop */

// ---------------- scratch (device globals; no allocation allowed) ------------
__device__ float g_keyx[Tlen*Mmod*QKd];   // [t][m][k]          8 MB
__device__ float g_val1[Mmod*Tlen*Dd];    // [m][t][d]         16 MB
__device__ float g_P[Tlen*Mmod*Gg];       // [t][m][g]         64 MB
__device__ float g_WgT[3*Mmod*Hh*Hh];     // [mat][m][o][h]    48 MB (transposed gate weights)
__device__ float g_Pb[Mmod*Gg];
__device__ float g_Cb[Mmod*Gg];
__device__ float g_cbuf[2*Mmod*Hh];       // double-buffered c
__device__ float g_zhh[Mmod*Gg];
__device__ float g_qbuf[Mmod*QKd];
__device__ float g_q2[Mmod*Hh];
__device__ float g_k2[Mmod*Hh];
__device__ float g_v2[Mmod*Hh];
__device__ int   g_barCnt;
__device__ unsigned g_barGen;

// ---------------- init ---------------------------------------------------------
__global__ void k_init(float* __restrict__ out, long long out_size,
                       const float* __restrict__ bq)
{
    long long i = (long long)blockIdx.x*blockDim.x + threadIdx.x;
    long long stride = (long long)gridDim.x*blockDim.x;
    for (long long j=i; j<out_size; j+=stride) out[j]=0.f;
    for (long long j=i; j<2*Mmod*Hh; j+=stride) g_cbuf[j]=0.f;
    for (long long j=i; j<Mmod*Gg; j+=stride)  g_zhh[j]=0.f;     // h0=0 -> zhh=0
    for (long long j=i; j<Mmod*QKd; j+=stride) g_qbuf[j]=bq[j];  // h0=0 -> q=bq
    for (long long j=i; j<Mmod*Hh; j+=stride){ g_k2[j]=0.f; g_v2[j]=0.f; g_q2[j]=0.f; }
    if (i==0){ g_barCnt=0; g_barGen=0u; }
}

// ---------------- transpose gate weights: WgT[mat][m][o][h] = W[m][h][o] -----
__global__ __launch_bounds__(256) void k_transp(
    const float* __restrict__ Wqg, const float* __restrict__ Wkg,
    const float* __restrict__ Wvg)
{
    __shared__ float tile[32][33];
    const int mm = blockIdx.z;               // mat*16+m, 0..47
    const int mat = mm >> 4, m = mm & 15;
    const float* W = (mat==0?Wqg:(mat==1?Wkg:Wvg)) + (long long)m*Hh*Hh;
    const int o0 = blockIdx.x*32, h0 = blockIdx.y*32;
    const int tx = threadIdx.x & 31, ty = threadIdx.x >> 5;   // 32x8
    for (int i=ty;i<32;i+=8)
        tile[i][tx] = W[(long long)(h0+i)*Hh + o0+tx];
    __syncthreads();
    float* dstb = g_WgT + ((long long)mm*Hh + o0)*Hh + h0;
    for (int i=ty;i<32;i+=8)
        dstb[(long long)i*Hh + tx] = tile[tx][i];
}

// ---------------- fp32 SGEMM: C[i,j] = sum_k A[i,k]*B[j,k] (+bias[j]) --------
__global__ __launch_bounds__(256) void sgemm128(
    const float* __restrict__ Aext, int useValA, long long strideAm,
    const float* __restrict__ Bbase, long long strideBm,
    const float* __restrict__ biasBase, int strideBias, int hasBias,
    int dstSel, long long strideCm, int ldc, int K)
{
    const int m  = blockIdx.z;
    const float* A = (useValA ? (const float*)g_val1 : Aext) + (long long)m*strideAm;
    const float* B = Bbase + (long long)m*strideBm;
    float* C = (dstSel==0 ? g_keyx : (dstSel==1 ? g_val1 : g_P)) + (long long)m*strideCm;

    const int i0 = blockIdx.y*128, j0 = blockIdx.x*128;
    __shared__ __align__(16) float As[8][128];
    __shared__ __align__(16) float Bs[8][128];
    const int tid = threadIdx.x;
    const int arow = tid>>1, acol = (tid&1)*4;
    const int tx = tid & 15, ty = tid >> 4;

    float acc[8][8];
    #pragma unroll
    for (int r=0;r<8;r++)
        #pragma unroll
        for (int c=0;c<8;c++) acc[r][c]=0.f;

    for (int kk=0; kk<K; kk+=8){
        float4 av = *(const float4*)(A + (long long)(i0+arow)*K + kk + acol);
        float4 bv = *(const float4*)(B + (long long)(j0+arow)*K + kk + acol);
        __syncthreads();
        As[acol+0][arow]=av.x; As[acol+1][arow]=av.y; As[acol+2][arow]=av.z; As[acol+3][arow]=av.w;
        Bs[acol+0][arow]=bv.x; Bs[acol+1][arow]=bv.y; Bs[acol+2][arow]=bv.z; Bs[acol+3][arow]=bv.w;
        __syncthreads();
        #pragma unroll
        for (int k=0;k<8;k++){
            float ar[8], br[8];
            *(float4*)&ar[0] = *(const float4*)&As[k][ty*8];
            *(float4*)&ar[4] = *(const float4*)&As[k][ty*8+4];
            *(float4*)&br[0] = *(const float4*)&Bs[k][tx*8];
            *(float4*)&br[4] = *(const float4*)&Bs[k][tx*8+4];
            #pragma unroll
            for (int r=0;r<8;r++)
                #pragma unroll
                for (int c=0;c<8;c++) acc[r][c] += ar[r]*br[c];
        }
    }
    #pragma unroll
    for (int r=0;r<8;r++){
        const int i = i0 + ty*8 + r;
        #pragma unroll
        for (int c=0;c<8;c++){
            const int j = j0 + tx*8 + c;
            float v = acc[r][c];
            if (hasBias) v += biasBase[(long long)m*strideBias + j];
            C[(long long)i*ldc + j] = v;
        }
    }
}

// ---------------- Pb[m,g] = bv[m]·W_ih[m,g,:];  Cb = b_ih + b_hh + Pb --------
__global__ __launch_bounds__(256) void k_pbcb(
    const float* __restrict__ bv, const float* __restrict__ Wih,
    const float* __restrict__ bih, const float* __restrict__ bhh)
{
    const int w = (blockIdx.x*blockDim.x + threadIdx.x) >> 5;
    const int lane = threadIdx.x & 31;
    if (w >= Mmod*Gg) return;
    const int m = w >> 11;
    const float* wrow = Wih + (long long)w*Dd;
    const float* bvr  = bv + (long long)m*Dd;
    float acc=0.f;
    #pragma unroll
    for (int i=0;i<4;i++){
        float4 a = *(const float4*)(wrow + (lane+32*i)*4);
        float4 b = *(const float4*)(bvr  + (lane+32*i)*4);
        acc += a.x*b.x + a.y*b.y + a.z*b.z + a.w*b.w;
    }
    #pragma unroll
    for (int off=16;off;off>>=1) acc += __shfl_down_sync(0xffffffffu, acc, off);
    if (lane==0){
        g_Pb[w] = acc;
        g_Cb[w] = acc + bih[w] + bhh[w];
    }
}

// ---------------- grid barrier (backoff polling) ------------------------------
__device__ __forceinline__ void gridbar(unsigned& gen)
{
    __threadfence();
    __syncthreads();
    if (threadIdx.x == 0){
        if (atomicAdd(&g_barCnt, 1) == NB-1){
            atomicExch(&g_barCnt, 0);
            __threadfence();
            atomicAdd(&g_barGen, 1u);
        } else {
            unsigned v; unsigned slp = 64;
            for (;;){
                asm volatile("ld.acquire.gpu.u32 %0, [%1];" : "=r"(v) : "l"(&g_barGen));
                if (v != gen) break;
                __nanosleep(slp);
                if (slp < 512u) slp <<= 1;
            }
        }
    }
    __syncthreads();
    gen++;
}

// ---------------- persistent step loop ---------------------------------------
__global__ __launch_bounds__(NT,1) void k_loop(
    const float* __restrict__ Wq,  const float* __restrict__ bq,
    const float* __restrict__ bk,  const float* __restrict__ Whh,
    float* __restrict__ out, long long osz)
{
    __shared__ __align__(16) float hloc[Mmod*Hh];   // persistent local h (32KB)
    __shared__ __align__(16) float th[KACT][Hh];    // temp_h of active modules (8KB)
    __shared__ float att0s[Mmod], att1s[Mmod];
    __shared__ float sl2[KACT*Mmod];
    __shared__ float att2s[KACT][Mmod];
    __shared__ int actFlag[Mmod], prevFlag[Mmod];
    __shared__ int actList[KACT], dirtyL[Mmod], slotOf[Mmod];
    __shared__ int nDirtyS;

    const int tid = threadIdx.x;
    const int lane = tid & 31, wid = tid >> 5;     // wid 0..15
    const int bx = blockIdx.x;
    const int gw = bx*16 + wid;                    // global warp id 0..2367
    unsigned gen = 0;

    for (int i=tid;i<Mmod*Hh;i+=NT) hloc[i]=0.f;
    if (tid<Mmod) prevFlag[tid]=0;
    __syncthreads();

    for (int t=0; t<Tlen; t++){
        // ======= region 1: z_hh/q GEMV for modules active at t-1 (h changed) ====
        if (t > 0){
            const int rows = KACT*2304;                  // 9216 rows
            const int per  = (rows + NB*16 - 1)/(NB*16); // 4
            int r    = gw*per;
            int rend = r + per; if (rend > rows) rend = rows;
            while (r < rend){
                int nr = rend - r; if (nr > 4) nr = 4;
                const float* wr[4]; const float* hv[4]; float* dst[4]; float bias[4];
                #pragma unroll
                for (int j=0;j<4;j++){
                    int rr = r + (j < nr ? j : 0);
                    int im = rr/2304;
                    int m  = actList[im];                // act(t-1)
                    int k  = rr - im*2304;
                    if (k < Gg){
                        wr[j]  = Whh + ((long long)m*Gg + k)*Hh;
                        dst[j] = &g_zhh[m*Gg + k];
                        bias[j]= 0.f;
                    } else {
                        int kk = k - Gg;
                        wr[j]  = Wq + ((long long)m*QKd + kk)*Hh;
                        dst[j] = &g_qbuf[m*QKd + kk];
                        bias[j]= bq[m*QKd + kk];
                    }
                    hv[j] = &hloc[m*Hh];
                }
                float4 a[4][4];
                #pragma unroll
                for (int j=0;j<4;j++)
                    #pragma unroll
                    for (int i=0;i<4;i++)
                        a[j][i] = *(const float4*)(wr[j] + (lane+32*i)*4);
                float acc[4] = {0.f,0.f,0.f,0.f};
                #pragma unroll
                for (int j=0;j<4;j++)
                    #pragma unroll
                    for (int i=0;i<4;i++){
                        float4 b = *(const float4*)(hv[j] + (lane+32*i)*4);
                        acc[j] += a[j][i].x*b.x + a[j][i].y*b.y + a[j][i].z*b.z + a[j][i].w*b.w;
                    }
                #pragma unroll
                for (int j=0;j<4;j++){
                    float v = acc[j];
                    #pragma unroll
                    for (int off=16;off;off>>=1) v += __shfl_down_sync(0xffffffffu, v, off);
                    if (lane==0 && j < nr) *dst[j] = v + bias[j];
                }
                r += nr;
            }
        }
        gridbar(gen);

        // ======= region 2: att (redundant) + D (redundant) + E (spread) =========
        // att: warp w handles module w
        {
            const int m = wid;
            const float* qb  = g_qbuf + m*QKd + lane*8;
            float4 q1  = __ldcg((const float4*)qb);
            float4 q2v = __ldcg((const float4*)(qb+4));
            const float* bkp = bk + m*QKd + lane*8;
            float4 b1 = *(const float4*)bkp;
            float4 b2 = *(const float4*)(bkp+4);
            const float* kx = g_keyx + ((long long)t*Mmod + m)*QKd + lane*8;
            float4 k1  = *(const float4*)kx;
            float4 k2v = *(const float4*)(kx+4);
            float p0 = q1.x*b1.x + q1.y*b1.y + q1.z*b1.z + q1.w*b1.w
                     + q2v.x*b2.x + q2v.y*b2.y + q2v.z*b2.z + q2v.w*b2.w;
            float p1 = q1.x*k1.x + q1.y*k1.y + q1.z*k1.z + q1.w*k1.w
                     + q2v.x*k2v.x + q2v.y*k2v.y + q2v.z*k2v.z + q2v.w*k2v.w;
            #pragma unroll
            for (int off=16;off;off>>=1){
                p0 += __shfl_down_sync(0xffffffffu,p0,off);
                p1 += __shfl_down_sync(0xffffffffu,p1,off);
            }
            if (lane==0){
                const float scale = 0.0625f;        /* 1/sqrt(256) */
                float l0 = p0*scale, l1 = p1*scale;
                float mx = fmaxf(l0,l1);
                float e0 = expf(l0-mx), e1 = expf(l1-mx);
                float s = e0+e1;
                att0s[m] = e0/s;
                att1s[m] = e1/s;
            }
        }
        __syncthreads();
        if (tid < Mmod){
            const float my0 = att0s[tid];
            int cnt=0;
            #pragma unroll
            for (int q=0;q<Mmod;q++) cnt += (att0s[q] < my0) || (att0s[q]==my0 && q<tid);
            actFlag[tid] = (cnt < KACT);
        }
        __syncthreads();
        if (tid==0){
            int na=0, n=0;
            for (int m=0;m<Mmod;m++){
                if (actFlag[m]){ slotOf[m]=na; actList[na++]=m; }
                if (actFlag[m] | prevFlag[m]) dirtyL[n++]=m;
            }
            nDirtyS = n;
        }
        // top-k index output (block 0, off-critical warp)
        if (bx==0 && tid==480 && osz >= (long long)Tlen*Mmod*Hh + (long long)Tlen*KACT){
            bool used[Mmod];
            #pragma unroll
            for (int q=0;q<Mmod;q++) used[q]=false;
            for (int r2=0;r2<KACT;r2++){
                float best = 3.4e38f; int bi=0;
                for (int q=0;q<Mmod;q++)
                    if (!used[q] && att0s[q] < best){ best=att0s[q]; bi=q; }
                used[bi]=true;
                out[(long long)Tlen*Mmod*Hh + (long long)t*KACT + r2] = (float)bi;
            }
        }
        __syncthreads();

        // D (gates/LSTM) redundant for the 4 active modules; 512 threads = 1 pass
        {
            const int rb = (t&1)*Mmod*Hh, wb = ((t+1)&1)*Mmod*Hh;
            const int jj = tid;
            #pragma unroll
            for (int s=0; s<KACT; s++){
                const int m = actList[s];
                const float att1 = att1s[m];
                const float* Cbp = g_Cb + m*Gg;
                const float* Pbp = g_Pb + m*Gg;
                const float* Pp  = g_P + (long long)t*Mmod*Gg + (long long)m*Gg;
                const float* zp  = g_zhh + m*Gg;
                float gv[4];
                #pragma unroll
                for (int q=0;q<4;q++){
                    const int g = jj + q*Hh;
                    gv[q] = Cbp[g] + att1*(__ldg(&Pp[g]) - Pbp[g]) + __ldcg(&zp[g]);
                }
                const float ig = 1.f/(1.f+expf(-gv[0]));
                const float fg = 1.f/(1.f+expf(-gv[1]));
                const float gg = tanhf(gv[2]);
                const float og = 1.f/(1.f+expf(-gv[3]));
                const float c_old = __ldcg(&g_cbuf[rb + m*Hh + jj]);
                const float cn = fg*c_old + ig*gg;
                const float hn = og*tanhf(cn);
                th[s][jj] = hn;
                if (bx == m) g_cbuf[wb + m*Hh + jj] = cn;
            }
            if (bx < Mmod && !actFlag[bx])
                g_cbuf[wb + bx*Hh + tid] = 0.f;
        }
        __syncthreads();

        // E: q2 (active) + k2/v2 (dirty) GEMV over transposed WgT, warp-spread
        {
            const int totalE = KACT*Hh + nDirtyS*2*Hh;     // 2048 + nDirty*1024
            const int per = (totalE + NB*16 - 1)/(NB*16);
            int r    = gw*per;
            int rend = r + per; if (rend > totalE) rend = totalE;
            while (r < rend){
                int nr = rend - r; if (nr > 4) nr = 4;
                const float* wr[4]; const float* tv[4]; float* dst[4];
                #pragma unroll
                for (int j=0;j<4;j++){
                    int rr = r + (j < nr ? j : 0);
                    if (rr < KACT*Hh){
                        int s = rr >> 9, o = rr & 511;
                        int m = actList[s];
                        wr[j]  = g_WgT + ((long long)m*Hh + o)*Hh;           // mat 0
                        tv[j]  = th[s];
                        dst[j] = &g_q2[m*Hh + o];
                    } else {
                        int v = rr - KACT*Hh;
                        int mi = v >> 10;
                        int m  = dirtyL[mi];
                        int rm = v & 1023;
                        int mat = 1 + (rm >> 9);
                        int o  = rm & 511;
                        wr[j]  = g_WgT + (((long long)mat*Mmod + m)*Hh + o)*Hh;
                        tv[j]  = actFlag[m] ? th[slotOf[m]] : &hloc[m*Hh];
                        dst[j] = (mat==1 ? g_k2 : g_v2) + m*Hh + o;
                    }
                }
                float4 a[4][4];
                #pragma unroll
                for (int j=0;j<4;j++)
                    #pragma unroll
                    for (int i=0;i<4;i++)
                        a[j][i] = *(const float4*)(wr[j] + (lane+32*i)*4);
                float acc[4] = {0.f,0.f,0.f,0.f};
                #pragma unroll
                for (int j=0;j<4;j++)
                    #pragma unroll
                    for (int i=0;i<4;i++){
                        float4 b = *(const float4*)(tv[j] + (lane+32*i)*4);
                        acc[j] += a[j][i].x*b.x + a[j][i].y*b.y + a[j][i].z*b.z + a[j][i].w*b.w;
                    }
                #pragma unroll
                for (int j=0;j<4;j++){
                    float v = acc[j];
                    #pragma unroll
                    for (int off=16;off;off>>=1) v += __shfl_down_sync(0xffffffffu, v, off);
                    if (lane==0 && j < nr) *dst[j] = v;
                }
                r += nr;
            }
        }
        gridbar(gen);

        // ======= region 3: F (redundant) + h update + output =====================
        #pragma unroll
        for (int p = wid*4; p < wid*4+4; p++){
            const int ai = p >> 4;
            const int b2 = p & 15;
            const float* q2p = g_q2 + actList[ai]*Hh;
            const float* kp2 = g_k2 + b2*Hh;
            float acc=0.f;
            #pragma unroll
            for (int i=0;i<4;i++){
                float4 kv4 = __ldcg((const float4*)(kp2 + (lane+32*i)*4));
                float4 qv4 = __ldcg((const float4*)(q2p + (lane+32*i)*4));
                acc += kv4.x*qv4.x + kv4.y*qv4.y + kv4.z*qv4.z + kv4.w*qv4.w;
            }
            #pragma unroll
            for (int off=16;off;off>>=1) acc += __shfl_down_sync(0xffffffffu, acc, off);
            if (lane==0) sl2[p] = acc;
        }
        __syncthreads();
        if (tid < KACT){
            float mx=-3.4e38f;
            for (int q=0;q<Mmod;q++) mx = fmaxf(mx, sl2[tid*Mmod+q]);
            float s=0.f;
            for (int q=0;q<Mmod;q++){ float e=expf(sl2[tid*Mmod+q]-mx); att2s[tid][q]=e; s+=e; }
            const float inv = 1.f/s;
            for (int q=0;q<Mmod;q++) att2s[tid][q]*=inv;
        }
        __syncthreads();
        #pragma unroll
        for (int i=0;i<KACT;i++){
            const int a = actList[i];
            const int o = tid;
            float s=0.f;
            #pragma unroll
            for (int q=0;q<Mmod;q++) s += att2s[i][q]*__ldcg(&g_v2[q*Hh+o]);
            hloc[a*Hh+o] = s + th[i][o];
        }
        __syncthreads();
        if (bx < Mmod)
            out[((long long)t*Mmod + bx)*Hh + tid] = hloc[bx*Hh + tid];
        if (tid < Mmod) prevFlag[tid] = actFlag[tid];
        __syncthreads();
        // no grid barrier here: region 1 of t+1 writes only zhh/qbuf,
        // never read in region 3; bar1 of t+1 gates region 2.
    }
}

// ---------------- launch ------------------------------------------------------
extern "C" void kernel_launch(void* const* d_in, const int* in_sizes, int n_in,
                              void* d_out, int out_size)
{
    const float* inputs = (const float*)d_in[0];
    const float* Wq   = (const float*)d_in[1];
    const float* bq   = (const float*)d_in[2];
    const float* Wk   = (const float*)d_in[3];
    const float* bk   = (const float*)d_in[4];
    const float* Wv   = (const float*)d_in[5];
    const float* bv   = (const float*)d_in[6];
    const float* Wih  = (const float*)d_in[7];
    const float* bih  = (const float*)d_in[8];
    const float* Whh  = (const float*)d_in[9];
    const float* bhh  = (const float*)d_in[10];
    const float* Wqg  = (const float*)d_in[11];
    const float* Wkg  = (const float*)d_in[12];
    const float* Wvg  = (const float*)d_in[13];
    float* out = (float*)d_out;
    const long long osz = (long long)out_size;

    k_init<<<1024,256>>>(out, osz, bq);

    {   // transpose gate weights once
        dim3 g(16,16,48);
        k_transp<<<g,256>>>(Wqg, Wkg, Wvg);
    }
    // key_x[t,m,k] = x_t @ Wk^T + bk
    {
        dim3 g(QKd/128, Tlen/128, Mmod);
        sgemm128<<<g,256>>>(inputs, 0, (long long)Tlen*Dd,
                            Wk, (long long)QKd*Dd,
                            bk, QKd, 1,
                            0, (long long)QKd, Mmod*QKd, Dd);
    }
    // val1[m,t,v] = x_t @ Wv^T + bv
    {
        dim3 g(Dd/128, Tlen/128, Mmod);
        sgemm128<<<g,256>>>(inputs, 0, (long long)Tlen*Dd,
                            Wv, (long long)Dd*Dd,
                            bv, Dd, 1,
                            1, (long long)Tlen*Dd, Dd, Dd);
    }
    k_pbcb<<<(Mmod*Gg)/8, 256>>>(bv, Wih, bih, bhh);
    // P[t,m,g] = val1 @ W_ih^T
    {
        dim3 g(Gg/128, Tlen/128, Mmod);
        sgemm128<<<g,256>>>(nullptr, 1, (long long)Tlen*Dd,
                            Wih, (long long)Gg*Dd,
                            nullptr, 0, 0,
                            2, (long long)Gg, Mmod*Gg, Dd);
    }

    k_loop<<<NB,NT>>>(Wq, bq, bk, Whh, out, osz);
}

// round 12
// speedup vs baseline: 2.5341x; 1.0168x over previous
#include <cuda_runtime.h>
#include <math.h>

#define Mmod 16
#define Tlen 512
#define Dd   512
#define Hh   512
#define QKd  256
#define Gg   2048   /* 4*H */
#define KACT 4
#define NB   148    /* persistent blocks; <= SM count, 1 block/SM guaranteed */
#define NT   512    /* threads per block in k_loop */

// ---------------- scratch (device globals; no allocation allowed) ------------
__device__ float g_keyx[Tlen*Mmod*QKd];   // [t][m][k]          8 MB   (streamed)
__device__ float g_val1[Mmod*Tlen*Dd];    // [m][t][d]         16 MB
__device__ float g_P[Tlen*Mmod*Gg];       // [t][m][g]         64 MB   (streamed)
__device__ float g_WgT[3*Mmod*Hh*Hh];     // [mat][m][o][h]    48 MB (transposed gate weights)
__device__ float g_Pb[Mmod*Gg];
__device__ float g_Cb[Mmod*Gg];
__device__ float g_cbuf[2*Mmod*Hh];       // double-buffered c
__device__ float g_zhh[Mmod*Gg];
__device__ float g_qbuf[Mmod*QKd];
__device__ float g_q2[Mmod*Hh];
__device__ float g_k2[Mmod*Hh];
__device__ float g_v2[Mmod*Hh];
__device__ int   g_barCnt;
__device__ unsigned g_barGen;

// ---------------- init ---------------------------------------------------------
__global__ void k_init(float* __restrict__ out, long long out_size,
                       const float* __restrict__ bq)
{
    long long i = (long long)blockIdx.x*blockDim.x + threadIdx.x;
    long long stride = (long long)gridDim.x*blockDim.x;
    for (long long j=i; j<out_size; j+=stride) __stcs(&out[j], 0.f);
    for (long long j=i; j<2*Mmod*Hh; j+=stride) g_cbuf[j]=0.f;
    for (long long j=i; j<Mmod*Gg; j+=stride)  g_zhh[j]=0.f;     // h0=0 -> zhh=0
    for (long long j=i; j<Mmod*QKd; j+=stride) g_qbuf[j]=bq[j];  // h0=0 -> q=bq
    for (long long j=i; j<Mmod*Hh; j+=stride){ g_k2[j]=0.f; g_v2[j]=0.f; g_q2[j]=0.f; }
    if (i==0){ g_barCnt=0; g_barGen=0u; }
}

// ---------------- transpose gate weights: WgT[mat][m][o][h] = W[m][h][o] -----
__global__ __launch_bounds__(256) void k_transp(
    const float* __restrict__ Wqg, const float* __restrict__ Wkg,
    const float* __restrict__ Wvg)
{
    __shared__ float tile[32][33];
    const int mm = blockIdx.z;               // mat*16+m, 0..47
    const int mat = mm >> 4, m = mm & 15;
    const float* W = (mat==0?Wqg:(mat==1?Wkg:Wvg)) + (long long)m*Hh*Hh;
    const int o0 = blockIdx.x*32, h0 = blockIdx.y*32;
    const int tx = threadIdx.x & 31, ty = threadIdx.x >> 5;   // 32x8
    for (int i=ty;i<32;i+=8)
        tile[i][tx] = W[(long long)(h0+i)*Hh + o0+tx];
    __syncthreads();
    float* dstb = g_WgT + ((long long)mm*Hh + o0)*Hh + h0;
    for (int i=ty;i<32;i+=8)
        dstb[(long long)i*Hh + tx] = tile[tx][i];
}

// ---------------- fp32 SGEMM: C[i,j] = sum_k A[i,k]*B[j,k] (+bias[j]) --------
// 128x128 tile, BK=8, register-prefetch double buffering, streaming C stores.
__global__ __launch_bounds__(256) void sgemm128(
    const float* __restrict__ Aext, int useValA, long long strideAm,
    const float* __restrict__ Bbase, long long strideBm,
    const float* __restrict__ biasBase, int strideBias, int hasBias,
    int dstSel, long long strideCm, int ldc, int K)
{
    const int m  = blockIdx.z;
    const float* A = (useValA ? (const float*)g_val1 : Aext) + (long long)m*strideAm;
    const float* B = Bbase + (long long)m*strideBm;
    float* C = (dstSel==0 ? g_keyx : (dstSel==1 ? g_val1 : g_P)) + (long long)m*strideCm;

    const int i0 = blockIdx.y*128, j0 = blockIdx.x*128;
    __shared__ __align__(16) float As[8][128];
    __shared__ __align__(16) float Bs[8][128];
    const int tid = threadIdx.x;
    const int arow = tid>>1, acol = (tid&1)*4;
    const int tx = tid & 15, ty = tid >> 4;

    const float* Arow = A + (long long)(i0+arow)*K + acol;
    const float* Brow = B + (long long)(j0+arow)*K + acol;

    float acc[8][8];
    #pragma unroll
    for (int r=0;r<8;r++)
        #pragma unroll
        for (int c=0;c<8;c++) acc[r][c]=0.f;

    float4 av = *(const float4*)(Arow);
    float4 bv = *(const float4*)(Brow);

    for (int kk=0; kk<K; kk+=8){
        __syncthreads();
        As[acol+0][arow]=av.x; As[acol+1][arow]=av.y; As[acol+2][arow]=av.z; As[acol+3][arow]=av.w;
        Bs[acol+0][arow]=bv.x; Bs[acol+1][arow]=bv.y; Bs[acol+2][arow]=bv.z; Bs[acol+3][arow]=bv.w;
        __syncthreads();
        float4 avn, bvn;
        if (kk+8 < K){
            avn = *(const float4*)(Arow + kk + 8);
            bvn = *(const float4*)(Brow + kk + 8);
        }
        #pragma unroll
        for (int k=0;k<8;k++){
            float ar[8], br[8];
            *(float4*)&ar[0] = *(const float4*)&As[k][ty*8];
            *(float4*)&ar[4] = *(const float4*)&As[k][ty*8+4];
            *(float4*)&br[0] = *(const float4*)&Bs[k][tx*8];
            *(float4*)&br[4] = *(const float4*)&Bs[k][tx*8+4];
            #pragma unroll
            for (int r=0;r<8;r++)
                #pragma unroll
                for (int c=0;c<8;c++) acc[r][c] += ar[r]*br[c];
        }
        av = avn; bv = bvn;
    }
    #pragma unroll
    for (int r=0;r<8;r++){
        const int i = i0 + ty*8 + r;
        #pragma unroll
        for (int c=0;c<8;c++){
            const int j = j0 + tx*8 + c;
            float v = acc[r][c];
            if (hasBias) v += biasBase[(long long)m*strideBias + j];
            __stcs(&C[(long long)i*ldc + j], v);
        }
    }
}

// ---------------- Pb[m,g] = bv[m]·W_ih[m,g,:];  Cb = b_ih + b_hh + Pb --------
__global__ __launch_bounds__(256) void k_pbcb(
    const float* __restrict__ bv, const float* __restrict__ Wih,
    const float* __restrict__ bih, const float* __restrict__ bhh)
{
    const int w = (blockIdx.x*blockDim.x + threadIdx.x) >> 5;
    const int lane = threadIdx.x & 31;
    if (w >= Mmod*Gg) return;
    const int m = w >> 11;
    const float* wrow = Wih + (long long)w*Dd;
    const float* bvr  = bv + (long long)m*Dd;
    float acc=0.f;
    #pragma unroll
    for (int i=0;i<4;i++){
        float4 a = *(const float4*)(wrow + (lane+32*i)*4);
        float4 b = *(const float4*)(bvr  + (lane+32*i)*4);
        acc += a.x*b.x + a.y*b.y + a.z*b.z + a.w*b.w;
    }
    #pragma unroll
    for (int off=16;off;off>>=1) acc += __shfl_down_sync(0xffffffffu, acc, off);
    if (lane==0){
        g_Pb[w] = acc;
        g_Cb[w] = acc + bih[w] + bhh[w];
    }
}

// ---------------- grid barrier (backoff polling) ------------------------------
__device__ __forceinline__ void gridbar(unsigned& gen)
{
    __threadfence();
    __syncthreads();
    if (threadIdx.x == 0){
        if (atomicAdd(&g_barCnt, 1) == NB-1){
            atomicExch(&g_barCnt, 0);
            __threadfence();
            atomicAdd(&g_barGen, 1u);
        } else {
            unsigned v; unsigned slp = 32;
            for (;;){
                asm volatile("ld.acquire.gpu.u32 %0, [%1];" : "=r"(v) : "l"(&g_barGen));
                if (v != gen) break;
                __nanosleep(slp);
                if (slp < 128u) slp <<= 1;
            }
        }
    }
    __syncthreads();
    gen++;
}

// ---------------- persistent step loop ---------------------------------------
__global__ __launch_bounds__(NT,1) void k_loop(
    const float* __restrict__ Wq,  const float* __restrict__ bq,
    const float* __restrict__ bk,  const float* __restrict__ Whh,
    float* __restrict__ out, long long osz)
{
    __shared__ __align__(16) float hloc[Mmod*Hh];   // persistent local h (32KB)
    __shared__ __align__(16) float th[KACT][Hh];    // temp_h of active modules (8KB)
    __shared__ float att0s[Mmod], att1s[Mmod];
    __shared__ float sl2[KACT*Mmod];
    __shared__ float att2s[KACT][Mmod];
    __shared__ int actFlag[Mmod], prevFlag[Mmod];
    __shared__ int actList[KACT], dirtyL[Mmod], slotOf[Mmod];
    __shared__ int nDirtyS;

    const int tid = threadIdx.x;
    const int lane = tid & 31, wid = tid >> 5;     // wid 0..15
    const int bx = blockIdx.x;
    const int gw = bx*16 + wid;                    // global warp id 0..2367
    unsigned gen = 0;

    for (int i=tid;i<Mmod*Hh;i+=NT) hloc[i]=0.f;
    if (tid<Mmod) prevFlag[tid]=0;
    __syncthreads();

    for (int t=0; t<Tlen; t++){
        // ======= region 1: z_hh/q GEMV for modules active at t-1 (h changed) ====
        if (t > 0){
            const int rows = KACT*2304;                  // 9216 rows
            const int per  = (rows + NB*16 - 1)/(NB*16); // 4
            int r    = gw*per;
            int rend = r + per; if (rend > rows) rend = rows;
            while (r < rend){
                int nr = rend - r; if (nr > 4) nr = 4;
                const float* wr[4]; const float* hv[4]; float* dst[4]; float bias[4];
                #pragma unroll
                for (int j=0;j<4;j++){
                    int rr = r + (j < nr ? j : 0);
                    int im = rr/2304;
                    int m  = actList[im];                // act(t-1)
                    int k  = rr - im*2304;
                    if (k < Gg){
                        wr[j]  = Whh + ((long long)m*Gg + k)*Hh;
                        dst[j] = &g_zhh[m*Gg + k];
                        bias[j]= 0.f;
                    } else {
                        int kk = k - Gg;
                        wr[j]  = Wq + ((long long)m*QKd + kk)*Hh;
                        dst[j] = &g_qbuf[m*QKd + kk];
                        bias[j]= bq[m*QKd + kk];
                    }
                    hv[j] = &hloc[m*Hh];
                }
                float4 a[4][4];
                #pragma unroll
                for (int j=0;j<4;j++)
                    #pragma unroll
                    for (int i=0;i<4;i++)
                        a[j][i] = *(const float4*)(wr[j] + (lane+32*i)*4);
                float acc[4] = {0.f,0.f,0.f,0.f};
                #pragma unroll
                for (int j=0;j<4;j++)
                    #pragma unroll
                    for (int i=0;i<4;i++){
                        float4 b = *(const float4*)(hv[j] + (lane+32*i)*4);
                        acc[j] += a[j][i].x*b.x + a[j][i].y*b.y + a[j][i].z*b.z + a[j][i].w*b.w;
                    }
                #pragma unroll
                for (int j=0;j<4;j++){
                    float v = acc[j];
                    #pragma unroll
                    for (int off=16;off;off>>=1) v += __shfl_down_sync(0xffffffffu, v, off);
                    if (lane==0 && j < nr) *dst[j] = v + bias[j];
                }
                r += nr;
            }
        }
        gridbar(gen);

        // ======= region 2: att (redundant) + D (redundant) + E (spread) =========
        // att: warp w handles module w
        {
            const int m = wid;
            const float* qb  = g_qbuf + m*QKd + lane*8;
            float4 q1  = __ldcg((const float4*)qb);
            float4 q2v = __ldcg((const float4*)(qb+4));
            const float* bkp = bk + m*QKd + lane*8;
            float4 b1 = *(const float4*)bkp;
            float4 b2 = *(const float4*)(bkp+4);
            const float* kx = g_keyx + ((long long)t*Mmod + m)*QKd + lane*8;
            float4 k1  = __ldcs((const float4*)kx);
            float4 k2v = __ldcs((const float4*)(kx+4));
            float p0 = q1.x*b1.x + q1.y*b1.y + q1.z*b1.z + q1.w*b1.w
                     + q2v.x*b2.x + q2v.y*b2.y + q2v.z*b2.z + q2v.w*b2.w;
            float p1 = q1.x*k1.x + q1.y*k1.y + q1.z*k1.z + q1.w*k1.w
                     + q2v.x*k2v.x + q2v.y*k2v.y + q2v.z*k2v.z + q2v.w*k2v.w;
            #pragma unroll
            for (int off=16;off;off>>=1){
                p0 += __shfl_down_sync(0xffffffffu,p0,off);
                p1 += __shfl_down_sync(0xffffffffu,p1,off);
            }
            if (lane==0){
                const float scale = 0.0625f;        /* 1/sqrt(256) */
                float l0 = p0*scale, l1 = p1*scale;
                float mx = fmaxf(l0,l1);
                float e0 = expf(l0-mx), e1 = expf(l1-mx);
                float s = e0+e1;
                att0s[m] = e0/s;
                att1s[m] = e1/s;
            }
        }
        __syncthreads();
        if (tid < Mmod){
            const float my0 = att0s[tid];
            int cnt=0;
            #pragma unroll
            for (int q=0;q<Mmod;q++) cnt += (att0s[q] < my0) || (att0s[q]==my0 && q<tid);
            actFlag[tid] = (cnt < KACT);
        }
        __syncthreads();
        if (tid==0){
            int na=0, n=0;
            for (int m=0;m<Mmod;m++){
                if (actFlag[m]){ slotOf[m]=na; actList[na++]=m; }
                if (actFlag[m] | prevFlag[m]) dirtyL[n++]=m;
            }
            nDirtyS = n;
        }
        // top-k index output (block 0, off-critical warp)
        if (bx==0 && tid==480 && osz >= (long long)Tlen*Mmod*Hh + (long long)Tlen*KACT){
            bool used[Mmod];
            #pragma unroll
            for (int q=0;q<Mmod;q++) used[q]=false;
            for (int r2=0;r2<KACT;r2++){
                float best = 3.4e38f; int bi=0;
                for (int q=0;q<Mmod;q++)
                    if (!used[q] && att0s[q] < best){ best=att0s[q]; bi=q; }
                used[bi]=true;
                out[(long long)Tlen*Mmod*Hh + (long long)t*KACT + r2] = (float)bi;
            }
        }
        __syncthreads();

        // D (gates/LSTM) redundant for the 4 active modules; 512 threads = 1 pass
        {
            const int rb = (t&1)*Mmod*Hh, wb = ((t+1)&1)*Mmod*Hh;
            const int jj = tid;
            #pragma unroll
            for (int s=0; s<KACT; s++){
                const int m = actList[s];
                const float att1 = att1s[m];
                const float* Cbp = g_Cb + m*Gg;
                const float* Pbp = g_Pb + m*Gg;
                const float* Pp  = g_P + (long long)t*Mmod*Gg + (long long)m*Gg;
                const float* zp  = g_zhh + m*Gg;
                float gv[4];
                #pragma unroll
                for (int q=0;q<4;q++){
                    const int g = jj + q*Hh;
                    gv[q] = Cbp[g] + att1*(__ldcs(&Pp[g]) - Pbp[g]) + __ldcg(&zp[g]);
                }
                const float ig = 1.f/(1.f+expf(-gv[0]));
                const float fg = 1.f/(1.f+expf(-gv[1]));
                const float gg = tanhf(gv[2]);
                const float og = 1.f/(1.f+expf(-gv[3]));
                const float c_old = __ldcg(&g_cbuf[rb + m*Hh + jj]);
                const float cn = fg*c_old + ig*gg;
                const float hn = og*tanhf(cn);
                th[s][jj] = hn;
                if (bx == m) g_cbuf[wb + m*Hh + jj] = cn;
            }
            if (bx < Mmod && !actFlag[bx])
                g_cbuf[wb + bx*Hh + tid] = 0.f;
        }
        __syncthreads();

        // E: q2 (active) + k2/v2 (dirty) GEMV over transposed WgT, warp-spread
        {
            const int totalE = KACT*Hh + nDirtyS*2*Hh;     // 2048 + nDirty*1024
            const int per = (totalE + NB*16 - 1)/(NB*16);
            int r    = gw*per;
            int rend = r + per; if (rend > totalE) rend = totalE;
            while (r < rend){
                int nr = rend - r; if (nr > 4) nr = 4;
                const float* wr[4]; const float* tv[4]; float* dst[4];
                #pragma unroll
                for (int j=0;j<4;j++){
                    int rr = r + (j < nr ? j : 0);
                    if (rr < KACT*Hh){
                        int s = rr >> 9, o = rr & 511;
                        int m = actList[s];
                        wr[j]  = g_WgT + ((long long)m*Hh + o)*Hh;           // mat 0
                        tv[j]  = th[s];
                        dst[j] = &g_q2[m*Hh + o];
                    } else {
                        int v = rr - KACT*Hh;
                        int mi = v >> 10;
                        int m  = dirtyL[mi];
                        int rm = v & 1023;
                        int mat = 1 + (rm >> 9);
                        int o  = rm & 511;
                        wr[j]  = g_WgT + (((long long)mat*Mmod + m)*Hh + o)*Hh;
                        tv[j]  = actFlag[m] ? th[slotOf[m]] : &hloc[m*Hh];
                        dst[j] = (mat==1 ? g_k2 : g_v2) + m*Hh + o;
                    }
                }
                float4 a[4][4];
                #pragma unroll
                for (int j=0;j<4;j++)
                    #pragma unroll
                    for (int i=0;i<4;i++)
                        a[j][i] = *(const float4*)(wr[j] + (lane+32*i)*4);
                float acc[4] = {0.f,0.f,0.f,0.f};
                #pragma unroll
                for (int j=0;j<4;j++)
                    #pragma unroll
                    for (int i=0;i<4;i++){
                        float4 b = *(const float4*)(tv[j] + (lane+32*i)*4);
                        acc[j] += a[j][i].x*b.x + a[j][i].y*b.y + a[j][i].z*b.z + a[j][i].w*b.w;
                    }
                #pragma unroll
                for (int j=0;j<4;j++){
                    float v = acc[j];
                    #pragma unroll
                    for (int off=16;off;off>>=1) v += __shfl_down_sync(0xffffffffu, v, off);
                    if (lane==0 && j < nr) *dst[j] = v;
                }
                r += nr;
            }
        }
        gridbar(gen);

        // ======= region 3: F (redundant) + h update + output =====================
        #pragma unroll
        for (int p = wid*4; p < wid*4+4; p++){
            const int ai = p >> 4;
            const int b2 = p & 15;
            const float* q2p = g_q2 + actList[ai]*Hh;
            const float* kp2 = g_k2 + b2*Hh;
            float acc=0.f;
            #pragma unroll
            for (int i=0;i<4;i++){
                float4 kv4 = __ldcg((const float4*)(kp2 + (lane+32*i)*4));
                float4 qv4 = __ldcg((const float4*)(q2p + (lane+32*i)*4));
                acc += kv4.x*qv4.x + kv4.y*qv4.y + kv4.z*qv4.z + kv4.w*qv4.w;
            }
            #pragma unroll
            for (int off=16;off;off>>=1) acc += __shfl_down_sync(0xffffffffu, acc, off);
            if (lane==0) sl2[p] = acc;
        }
        __syncthreads();
        if (tid < KACT){
            float mx=-3.4e38f;
            for (int q=0;q<Mmod;q++) mx = fmaxf(mx, sl2[tid*Mmod+q]);
            float s=0.f;
            for (int q=0;q<Mmod;q++){ float e=expf(sl2[tid*Mmod+q]-mx); att2s[tid][q]=e; s+=e; }
            const float inv = 1.f/s;
            for (int q=0;q<Mmod;q++) att2s[tid][q]*=inv;
        }
        __syncthreads();
        #pragma unroll
        for (int i=0;i<KACT;i++){
            const int a = actList[i];
            const int o = tid;
            float s=0.f;
            #pragma unroll
            for (int q=0;q<Mmod;q++) s += att2s[i][q]*__ldcg(&g_v2[q*Hh+o]);
            hloc[a*Hh+o] = s + th[i][o];
        }
        __syncthreads();
        if (bx < Mmod)
            __stcs(&out[((long long)t*Mmod + bx)*Hh + tid], hloc[bx*Hh + tid]);
        if (tid < Mmod) prevFlag[tid] = actFlag[tid];
        __syncthreads();
        // no grid barrier here: region 1 of t+1 writes only zhh/qbuf,
        // never read in region 3; bar1 of t+1 gates region 2.
    }
}

// ---------------- launch ------------------------------------------------------
extern "C" void kernel_launch(void* const* d_in, const int* in_sizes, int n_in,
                              void* d_out, int out_size)
{
    const float* inputs = (const float*)d_in[0];
    const float* Wq   = (const float*)d_in[1];
    const float* bq   = (const float*)d_in[2];
    const float* Wk   = (const float*)d_in[3];
    const float* bk   = (const float*)d_in[4];
    const float* Wv   = (const float*)d_in[5];
    const float* bv   = (const float*)d_in[6];
    const float* Wih  = (const float*)d_in[7];
    const float* bih  = (const float*)d_in[8];
    const float* Whh  = (const float*)d_in[9];
    const float* bhh  = (const float*)d_in[10];
    const float* Wqg  = (const float*)d_in[11];
    const float* Wkg  = (const float*)d_in[12];
    const float* Wvg  = (const float*)d_in[13];
    float* out = (float*)d_out;
    const long long osz = (long long)out_size;

    k_init<<<1024,256>>>(out, osz, bq);

    {   // transpose gate weights once
        dim3 g(16,16,48);
        k_transp<<<g,256>>>(Wqg, Wkg, Wvg);
    }
    // key_x[t,m,k] = x_t @ Wk^T + bk
    {
        dim3 g(QKd/128, Tlen/128, Mmod);
        sgemm128<<<g,256>>>(inputs, 0, (long long)Tlen*Dd,
                            Wk, (long long)QKd*Dd,
                            bk, QKd, 1,
                            0, (long long)QKd, Mmod*QKd, Dd);
    }
    // val1[m,t,v] = x_t @ Wv^T + bv
    {
        dim3 g(Dd/128, Tlen/128, Mmod);
        sgemm128<<<g,256>>>(inputs, 0, (long long)Tlen*Dd,
                            Wv, (long long)Dd*Dd,
                            bv, Dd, 1,
                            1, (long long)Tlen*Dd, Dd, Dd);
    }
    k_pbcb<<<(Mmod*Gg)/8, 256>>>(bv, Wih, bih, bhh);
    // P[t,m,g] = val1 @ W_ih^T
    {
        dim3 g(Gg/128, Tlen/128, Mmod);
        sgemm128<<<g,256>>>(nullptr, 1, (long long)Tlen*Dd,
                            Wih, (long long)Gg*Dd,
                            nullptr, 0, 0,
                            2, (long long)Gg, Mmod*Gg, Dd);
    }

    k_loop<<<NB,NT>>>(Wq, bq, bk, Whh, out, osz);
}

// round 17
// speedup vs baseline: 2.5425x; 1.0033x over previous
#include <cuda_runtime.h>
#include <math.h>

#define Mmod 16
#define Tlen 512
#define Dd   512
#define Hh   512
#define QKd  256
#define Gg   2048   /* 4*H */
#define KACT 4
#define NB   148    /* persistent blocks; <= SM count, 1 block/SM guaranteed */
#define NT   512    /* threads per block in k_loop */

// ---------------- scratch (device globals; no allocation allowed) ------------
__device__ float g_keyx[Tlen*Mmod*QKd];   // [t][m][k]          8 MB   (streamed)
__device__ float g_val1[Mmod*Tlen*Dd];    // [m][t][d]         16 MB
__device__ float g_P[Tlen*Mmod*Gg];       // P2=[t][m][g]-Pb   64 MB   (streamed)
__device__ float g_WgT[3*Mmod*Hh*Hh];     // [mat][m][o][h]    48 MB (transposed gate weights)
__device__ float g_Pb[Mmod*Gg];
__device__ float g_Cb[Mmod*Gg];
__device__ float g_cbuf[2*Mmod*Hh];       // double-buffered c
__device__ float g_zhh[Mmod*Gg];          // zhh' = h@Whh + Cb
__device__ float g_qbuf[Mmod*QKd];
__device__ float g_q2[Mmod*Hh];
__device__ float g_k2[Mmod*Hh];
__device__ float g_v2[Mmod*Hh];
__device__ int   g_barCnt;
__device__ unsigned g_barGen;

// ---------------- merged init + Pb/Cb/zhh' -----------------------------------
// grid 4096 x 256: warps 0..32767 each own one row w of Wih (Pb/Cb/zhh'),
// plus grid-stride init of out/cbuf/qbuf/q2k2v2.
__global__ __launch_bounds__(256) void k_initAll(
    float* __restrict__ out, long long osz, const float* __restrict__ bq,
    const float* __restrict__ bv, const float* __restrict__ Wih,
    const float* __restrict__ bih, const float* __restrict__ bhh)
{
    const long long gtid = (long long)blockIdx.x*256 + threadIdx.x;
    const int w = (int)(gtid >> 5);
    const int lane = threadIdx.x & 31;
    if (w < Mmod*Gg){
        const int m = w >> 11;
        const float* wrow = Wih + (long long)w*Dd;
        const float* bvr  = bv + (long long)m*Dd;
        float acc=0.f;
        #pragma unroll
        for (int i=0;i<4;i++){
            float4 a = *(const float4*)(wrow + (lane+32*i)*4);
            float4 b = *(const float4*)(bvr  + (lane+32*i)*4);
            acc += a.x*b.x + a.y*b.y + a.z*b.z + a.w*b.w;
        }
        #pragma unroll
        for (int off=16;off;off>>=1) acc += __shfl_down_sync(0xffffffffu, acc, off);
        if (lane==0){
            g_Pb[w] = acc;
            const float cb = acc + bih[w] + bhh[w];
            g_Cb[w]  = cb;
            g_zhh[w] = cb;          // h0=0 -> zhh' = Cb
        }
    }
    const long long stride = (long long)gridDim.x*256;
    for (long long j=gtid; j<osz; j+=stride) __stcs(&out[j], 0.f);
    for (long long j=gtid; j<2*Mmod*Hh; j+=stride) g_cbuf[j]=0.f;
    for (long long j=gtid; j<Mmod*QKd; j+=stride) g_qbuf[j]=bq[j];  // h0=0 -> q=bq
    for (long long j=gtid; j<Mmod*Hh; j+=stride){ g_k2[j]=0.f; g_v2[j]=0.f; g_q2[j]=0.f; }
    if (gtid==0){ g_barCnt=0; g_barGen=0u; }
}

// ---------------- transpose gate weights: WgT[mat][m][o][h] = W[m][h][o] -----
__global__ __launch_bounds__(256) void k_transp(
    const float* __restrict__ Wqg, const float* __restrict__ Wkg,
    const float* __restrict__ Wvg)
{
    __shared__ float tile[32][33];
    const int mm = blockIdx.z;               // mat*16+m, 0..47
    const int mat = mm >> 4, m = mm & 15;
    const float* W = (mat==0?Wqg:(mat==1?Wkg:Wvg)) + (long long)m*Hh*Hh;
    const int o0 = blockIdx.x*32, h0 = blockIdx.y*32;
    const int tx = threadIdx.x & 31, ty = threadIdx.x >> 5;   // 32x8
    for (int i=ty;i<32;i+=8)
        tile[i][tx] = W[(long long)(h0+i)*Hh + o0+tx];
    __syncthreads();
    float* dstb = g_WgT + ((long long)mm*Hh + o0)*Hh + h0;
    for (int i=ty;i<32;i+=8)
        dstb[(long long)i*Hh + tx] = tile[tx][i];
}

// ---------------- fp32 SGEMM: C[i,j] = sum_k A[i,k]*B[j,k] (+/- bias[j]) -----
// 128x128 tile, BK=8, register-prefetch double buffering, streaming C stores.
// biasMode: 0 none, 1 add biasBase, 2 subtract g_Pb (device-resolved symbol).
__global__ __launch_bounds__(256) void sgemm128(
    const float* __restrict__ Aext, int useValA, long long strideAm,
    const float* __restrict__ Bbase, long long strideBm,
    const float* __restrict__ biasBase, int strideBias, int biasMode,
    int dstSel, long long strideCm, int ldc, int K)
{
    const int m  = blockIdx.z;
    const float* A = (useValA ? (const float*)g_val1 : Aext) + (long long)m*strideAm;
    const float* B = Bbase + (long long)m*strideBm;
    float* C = (dstSel==0 ? g_keyx : (dstSel==1 ? g_val1 : g_P)) + (long long)m*strideCm;
    // Device-side resolution of the Pb bias (cannot pass __device__ symbol from host)
    const float* biasPtr = (biasMode==2) ? (const float*)g_Pb : biasBase;

    const int i0 = blockIdx.y*128, j0 = blockIdx.x*128;
    __shared__ __align__(16) float As[8][128];
    __shared__ __align__(16) float Bs[8][128];
    const int tid = threadIdx.x;
    const int arow = tid>>1, acol = (tid&1)*4;
    const int tx = tid & 15, ty = tid >> 4;

    const float* Arow = A + (long long)(i0+arow)*K + acol;
    const float* Brow = B + (long long)(j0+arow)*K + acol;

    float acc[8][8];
    #pragma unroll
    for (int r=0;r<8;r++)
        #pragma unroll
        for (int c=0;c<8;c++) acc[r][c]=0.f;

    float4 av = *(const float4*)(Arow);
    float4 bv = *(const float4*)(Brow);

    for (int kk=0; kk<K; kk+=8){
        __syncthreads();
        As[acol+0][arow]=av.x; As[acol+1][arow]=av.y; As[acol+2][arow]=av.z; As[acol+3][arow]=av.w;
        Bs[acol+0][arow]=bv.x; Bs[acol+1][arow]=bv.y; Bs[acol+2][arow]=bv.z; Bs[acol+3][arow]=bv.w;
        __syncthreads();
        float4 avn, bvn;
        if (kk+8 < K){
            avn = *(const float4*)(Arow + kk + 8);
            bvn = *(const float4*)(Brow + kk + 8);
        }
        #pragma unroll
        for (int k=0;k<8;k++){
            float ar[8], br[8];
            *(float4*)&ar[0] = *(const float4*)&As[k][ty*8];
            *(float4*)&ar[4] = *(const float4*)&As[k][ty*8+4];
            *(float4*)&br[0] = *(const float4*)&Bs[k][tx*8];
            *(float4*)&br[4] = *(const float4*)&Bs[k][tx*8+4];
            #pragma unroll
            for (int r=0;r<8;r++)
                #pragma unroll
                for (int c=0;c<8;c++) acc[r][c] += ar[r]*br[c];
        }
        av = avn; bv = bvn;
    }
    #pragma unroll
    for (int r=0;r<8;r++){
        const int i = i0 + ty*8 + r;
        #pragma unroll
        for (int c=0;c<8;c++){
            const int j = j0 + tx*8 + c;
            float v = acc[r][c];
            if (biasMode==1) v += biasPtr[(long long)m*strideBias + j];
            else if (biasMode==2) v -= biasPtr[(long long)m*strideBias + j];
            __stcs(&C[(long long)i*ldc + j], v);
        }
    }
}

// ---------------- grid barrier (backoff polling) ------------------------------
__device__ __forceinline__ void gridbar(unsigned& gen)
{
    __threadfence();
    __syncthreads();
    if (threadIdx.x == 0){
        if (atomicAdd(&g_barCnt, 1) == NB-1){
            atomicExch(&g_barCnt, 0);
            __threadfence();
            atomicAdd(&g_barGen, 1u);
        } else {
            unsigned v; unsigned slp = 32;
            for (;;){
                asm volatile("ld.acquire.gpu.u32 %0, [%1];" : "=r"(v) : "l"(&g_barGen));
                if (v != gen) break;
                __nanosleep(slp);
                if (slp < 128u) slp <<= 1;
            }
        }
    }
    __syncthreads();
    gen++;
}

// ---------------- persistent step loop ---------------------------------------
__global__ __launch_bounds__(NT,1) void k_loop(
    const float* __restrict__ Wq,  const float* __restrict__ bq,
    const float* __restrict__ bk,  const float* __restrict__ Whh,
    float* __restrict__ out, long long osz)
{
    __shared__ __align__(16) float hloc[Mmod*Hh];   // persistent local h (32KB)
    __shared__ __align__(16) float th[KACT][Hh];    // temp_h of active modules (8KB)
    __shared__ float att0s[Mmod], att1s[Mmod];
    __shared__ float sl2[KACT*Mmod];
    __shared__ float att2s[KACT][Mmod];
    __shared__ int actFlag[Mmod], prevFlag[Mmod];
    __shared__ int actList[KACT], dirtyL[Mmod], slotOf[Mmod];
    __shared__ int nDirtyS;

    const int tid = threadIdx.x;
    const int lane = tid & 31, wid = tid >> 5;     // wid 0..15
    const int bx = blockIdx.x;
    const int gw = bx*16 + wid;                    // global warp id 0..2367
    unsigned gen = 0;

    for (int i=tid;i<Mmod*Hh;i+=NT) hloc[i]=0.f;
    if (tid<Mmod) prevFlag[tid]=0;
    __syncthreads();

    for (int t=0; t<Tlen; t++){
        // ======= region 1: zhh'/q GEMV for modules active at t-1 (h changed) ====
        if (t > 0){
            const int rows = KACT*2304;                  // 9216 rows
            const int per  = (rows + NB*16 - 1)/(NB*16); // 4
            int r    = gw*per;
            int rend = r + per; if (rend > rows) rend = rows;
            while (r < rend){
                int nr = rend - r; if (nr > 4) nr = 4;
                const float* wr[4]; const float* hv[4]; float* dst[4]; float bias[4];
                #pragma unroll
                for (int j=0;j<4;j++){
                    int rr = r + (j < nr ? j : 0);
                    int im = rr/2304;
                    int m  = actList[im];                // act(t-1)
                    int k  = rr - im*2304;
                    if (k < Gg){
                        wr[j]  = Whh + ((long long)m*Gg + k)*Hh;
                        dst[j] = &g_zhh[m*Gg + k];
                        bias[j]= g_Cb[m*Gg + k];         // fold Cb into zhh'
                    } else {
                        int kk = k - Gg;
                        wr[j]  = Wq + ((long long)m*QKd + kk)*Hh;
                        dst[j] = &g_qbuf[m*QKd + kk];
                        bias[j]= bq[m*QKd + kk];
                    }
                    hv[j] = &hloc[m*Hh];
                }
                float4 a[4][4];
                #pragma unroll
                for (int j=0;j<4;j++)
                    #pragma unroll
                    for (int i=0;i<4;i++)
                        a[j][i] = *(const float4*)(wr[j] + (lane+32*i)*4);
                float acc[4] = {0.f,0.f,0.f,0.f};
                #pragma unroll
                for (int j=0;j<4;j++)
                    #pragma unroll
                    for (int i=0;i<4;i++){
                        float4 b = *(const float4*)(hv[j] + (lane+32*i)*4);
                        acc[j] += a[j][i].x*b.x + a[j][i].y*b.y + a[j][i].z*b.z + a[j][i].w*b.w;
                    }
                #pragma unroll
                for (int j=0;j<4;j++){
                    float v = acc[j];
                    #pragma unroll
                    for (int off=16;off;off>>=1) v += __shfl_down_sync(0xffffffffu, v, off);
                    if (lane==0 && j < nr) *dst[j] = v + bias[j];
                }
                r += nr;
            }
        }
        gridbar(gen);

        // ======= region 2: att (redundant) + D (redundant) + E (spread) =========
        // att: warp w handles module w
        {
            const int m = wid;
            const float* qb  = g_qbuf + m*QKd + lane*8;
            float4 q1  = __ldcg((const float4*)qb);
            float4 q2v = __ldcg((const float4*)(qb+4));
            const float* bkp = bk + m*QKd + lane*8;
            float4 b1 = *(const float4*)bkp;
            float4 b2 = *(const float4*)(bkp+4);
            const float* kx = g_keyx + ((long long)t*Mmod + m)*QKd + lane*8;
            float4 k1  = __ldcs((const float4*)kx);
            float4 k2v = __ldcs((const float4*)(kx+4));
            float p0 = q1.x*b1.x + q1.y*b1.y + q1.z*b1.z + q1.w*b1.w
                     + q2v.x*b2.x + q2v.y*b2.y + q2v.z*b2.z + q2v.w*b2.w;
            float p1 = q1.x*k1.x + q1.y*k1.y + q1.z*k1.z + q1.w*k1.w
                     + q2v.x*k2v.x + q2v.y*k2v.y + q2v.z*k2v.z + q2v.w*k2v.w;
            #pragma unroll
            for (int off=16;off;off>>=1){
                p0 += __shfl_down_sync(0xffffffffu,p0,off);
                p1 += __shfl_down_sync(0xffffffffu,p1,off);
            }
            if (lane==0){
                const float scale = 0.0625f;        /* 1/sqrt(256) */
                float l0 = p0*scale, l1 = p1*scale;
                float mx = fmaxf(l0,l1);
                float e0 = expf(l0-mx), e1 = expf(l1-mx);
                float s = e0+e1;
                att0s[m] = e0/s;
                att1s[m] = e1/s;
            }
        }
        __syncthreads();
        if (tid < Mmod){
            const float my0 = att0s[tid];
            int cnt=0;
            #pragma unroll
            for (int q=0;q<Mmod;q++) cnt += (att0s[q] < my0) || (att0s[q]==my0 && q<tid);
            actFlag[tid] = (cnt < KACT);
        }
        __syncthreads();
        if (tid==0){
            int na=0, n=0;
            for (int m=0;m<Mmod;m++){
                if (actFlag[m]){ slotOf[m]=na; actList[na++]=m; }
                if (actFlag[m] | prevFlag[m]) dirtyL[n++]=m;
            }
            nDirtyS = n;
        }
        // top-k index output (block 0, off-critical warp)
        if (bx==0 && tid==480 && osz >= (long long)Tlen*Mmod*Hh + (long long)Tlen*KACT){
            bool used[Mmod];
            #pragma unroll
            for (int q=0;q<Mmod;q++) used[q]=false;
            for (int r2=0;r2<KACT;r2++){
                float best = 3.4e38f; int bi=0;
                for (int q=0;q<Mmod;q++)
                    if (!used[q] && att0s[q] < best){ best=att0s[q]; bi=q; }
                used[bi]=true;
                out[(long long)Tlen*Mmod*Hh + (long long)t*KACT + r2] = (float)bi;
            }
        }
        __syncthreads();

        // D (gates/LSTM) redundant for the 4 active modules; gate = att1*P2 + zhh'
        {
            const int rb = (t&1)*Mmod*Hh, wb = ((t+1)&1)*Mmod*Hh;
            const int jj = tid;
            #pragma unroll
            for (int s=0; s<KACT; s++){
                const int m = actList[s];
                const float att1 = att1s[m];
                const float* Pp  = g_P + (long long)t*Mmod*Gg + (long long)m*Gg;
                const float* zp  = g_zhh + m*Gg;
                float gv[4];
                #pragma unroll
                for (int q=0;q<4;q++){
                    const int g = jj + q*Hh;
                    gv[q] = att1*__ldcs(&Pp[g]) + __ldcg(&zp[g]);
                }
                const float ig = 1.f/(1.f+expf(-gv[0]));
                const float fg = 1.f/(1.f+expf(-gv[1]));
                const float gg = tanhf(gv[2]);
                const float og = 1.f/(1.f+expf(-gv[3]));
                const float c_old = __ldcg(&g_cbuf[rb + m*Hh + jj]);
                const float cn = fg*c_old + ig*gg;
                const float hn = og*tanhf(cn);
                th[s][jj] = hn;
                if (bx == m) g_cbuf[wb + m*Hh + jj] = cn;
            }
            if (bx < Mmod && !actFlag[bx])
                g_cbuf[wb + bx*Hh + tid] = 0.f;
        }
        __syncthreads();

        // E: q2 (active) + k2/v2 (dirty) GEMV over transposed WgT, warp-spread
        {
            const int totalE = KACT*Hh + nDirtyS*2*Hh;     // 2048 + nDirty*1024
            const int per = (totalE + NB*16 - 1)/(NB*16);
            int r    = gw*per;
            int rend = r + per; if (rend > totalE) rend = totalE;
            while (r < rend){
                int nr = rend - r; if (nr > 4) nr = 4;
                const float* wr[4]; const float* tv[4]; float* dst[4];
                #pragma unroll
                for (int j=0;j<4;j++){
                    int rr = r + (j < nr ? j : 0);
                    if (rr < KACT*Hh){
                        int s = rr >> 9, o = rr & 511;
                        int m = actList[s];
                        wr[j]  = g_WgT + ((long long)m*Hh + o)*Hh;           // mat 0
                        tv[j]  = th[s];
                        dst[j] = &g_q2[m*Hh + o];
                    } else {
                        int v = rr - KACT*Hh;
                        int mi = v >> 10;
                        int m  = dirtyL[mi];
                        int rm = v & 1023;
                        int mat = 1 + (rm >> 9);
                        int o  = rm & 511;
                        wr[j]  = g_WgT + (((long long)mat*Mmod + m)*Hh + o)*Hh;
                        tv[j]  = actFlag[m] ? th[slotOf[m]] : &hloc[m*Hh];
                        dst[j] = (mat==1 ? g_k2 : g_v2) + m*Hh + o;
                    }
                }
                float4 a[4][4];
                #pragma unroll
                for (int j=0;j<4;j++)
                    #pragma unroll
                    for (int i=0;i<4;i++)
                        a[j][i] = *(const float4*)(wr[j] + (lane+32*i)*4);
                float acc[4] = {0.f,0.f,0.f,0.f};
                #pragma unroll
                for (int j=0;j<4;j++)
                    #pragma unroll
                    for (int i=0;i<4;i++){
                        float4 b = *(const float4*)(tv[j] + (lane+32*i)*4);
                        acc[j] += a[j][i].x*b.x + a[j][i].y*b.y + a[j][i].z*b.z + a[j][i].w*b.w;
                    }
                #pragma unroll
                for (int j=0;j<4;j++){
                    float v = acc[j];
                    #pragma unroll
                    for (int off=16;off;off>>=1) v += __shfl_down_sync(0xffffffffu, v, off);
                    if (lane==0 && j < nr) *dst[j] = v;
                }
                r += nr;
            }
        }
        gridbar(gen);

        // ======= region 3: F (redundant) + h update + output =====================
        #pragma unroll
        for (int p = wid*4; p < wid*4+4; p++){
            const int ai = p >> 4;
            const int b2 = p & 15;
            const float* q2p = g_q2 + actList[ai]*Hh;
            const float* kp2 = g_k2 + b2*Hh;
            float acc=0.f;
            #pragma unroll
            for (int i=0;i<4;i++){
                float4 kv4 = __ldcg((const float4*)(kp2 + (lane+32*i)*4));
                float4 qv4 = __ldcg((const float4*)(q2p + (lane+32*i)*4));
                acc += kv4.x*qv4.x + kv4.y*qv4.y + kv4.z*qv4.z + kv4.w*qv4.w;
            }
            #pragma unroll
            for (int off=16;off;off>>=1) acc += __shfl_down_sync(0xffffffffu, acc, off);
            if (lane==0) sl2[p] = acc;
        }
        __syncthreads();
        if (tid < KACT){
            float mx=-3.4e38f;
            for (int q=0;q<Mmod;q++) mx = fmaxf(mx, sl2[tid*Mmod+q]);
            float s=0.f;
            for (int q=0;q<Mmod;q++){ float e=expf(sl2[tid*Mmod+q]-mx); att2s[tid][q]=e; s+=e; }
            const float inv = 1.f/s;
            for (int q=0;q<Mmod;q++) att2s[tid][q]*=inv;
        }
        __syncthreads();
        {
            // register-cache v2 column o=tid across the 4 active modules
            float v2r[Mmod];
            #pragma unroll
            for (int q=0;q<Mmod;q++) v2r[q] = __ldcg(&g_v2[q*Hh + tid]);
            #pragma unroll
            for (int i=0;i<KACT;i++){
                const int a = actList[i];
                float s=0.f;
                #pragma unroll
                for (int q=0;q<Mmod;q++) s += att2s[i][q]*v2r[q];
                hloc[a*Hh+tid] = s + th[i][tid];
            }
        }
        __syncthreads();
        if (bx < Mmod)
            __stcs(&out[((long long)t*Mmod + bx)*Hh + tid], hloc[bx*Hh + tid]);
        if (tid < Mmod) prevFlag[tid] = actFlag[tid];
        __syncthreads();
        // no grid barrier here: region 1 of t+1 writes only zhh/qbuf,
        // never read in region 3; bar1 of t+1 gates region 2.
    }
}

// ---------------- launch ------------------------------------------------------
// Launch order chosen so k_loop is launch #6 (ncu -s 5 -c 1 captures it).
extern "C" void kernel_launch(void* const* d_in, const int* in_sizes, int n_in,
                              void* d_out, int out_size)
{
    const float* inputs = (const float*)d_in[0];
    const float* Wq   = (const float*)d_in[1];
    const float* bq   = (const float*)d_in[2];
    const float* Wk   = (const float*)d_in[3];
    const float* bk   = (const float*)d_in[4];
    const float* Wv   = (const float*)d_in[5];
    const float* bv   = (const float*)d_in[6];
    const float* Wih  = (const float*)d_in[7];
    const float* bih  = (const float*)d_in[8];
    const float* Whh  = (const float*)d_in[9];
    const float* bhh  = (const float*)d_in[10];
    const float* Wqg  = (const float*)d_in[11];
    const float* Wkg  = (const float*)d_in[12];
    const float* Wvg  = (const float*)d_in[13];
    float* out = (float*)d_out;
    const long long osz = (long long)out_size;

    // 1: init + Pb/Cb/zhh'
    k_initAll<<<4096,256>>>(out, osz, bq, bv, Wih, bih, bhh);

    // 2: transpose gate weights
    {
        dim3 g(16,16,48);
        k_transp<<<g,256>>>(Wqg, Wkg, Wvg);
    }
    // 3: key_x[t,m,k] = x_t @ Wk^T + bk
    {
        dim3 g(QKd/128, Tlen/128, Mmod);
        sgemm128<<<g,256>>>(inputs, 0, (long long)Tlen*Dd,
                            Wk, (long long)QKd*Dd,
                            bk, QKd, 1,
                            0, (long long)QKd, Mmod*QKd, Dd);
    }
    // 4: val1[m,t,v] = x_t @ Wv^T + bv
    {
        dim3 g(Dd/128, Tlen/128, Mmod);
        sgemm128<<<g,256>>>(inputs, 0, (long long)Tlen*Dd,
                            Wv, (long long)Dd*Dd,
                            bv, Dd, 1,
                            1, (long long)Tlen*Dd, Dd, Dd);
    }
    // 5: P2[t,m,g] = val1 @ W_ih^T - Pb (Pb resolved device-side via biasMode=2)
    {
        dim3 g(Gg/128, Tlen/128, Mmod);
        sgemm128<<<g,256>>>(nullptr, 1, (long long)Tlen*Dd,
                            Wih, (long long)Gg*Dd,
                            nullptr, Gg, 2,
                            2, (long long)Gg, Mmod*Gg, Dd);
    }

    // 6: persistent loop (profiled by ncu -s 5 -c 1)
    k_loop<<<NB,NT>>>(Wq, bq, bk, Whh, out, osz);
}